// round 1
// baseline (speedup 1.0000x reference)
#include <cuda_runtime.h>

#define NGT 512
#define NN  399
#define NSP 200
#define NED 397
#define DD  64
#define NL  2
#define EPT 398
#define ECOLS (NGT*EPT*2)      /* 407552 total directed edges = row length */
#define RS  65                 /* padded row stride (bank-conflict-free) */

typedef unsigned char u8;

/* ---------------- scratch (static device globals; no allocation) -------- */
__device__ float g_pool[(size_t)NSP*NGT*DD];   /* [s][g][d]  ~26 MB, L2-resident */
__device__ float g_valid[NSP*NGT];             /* [s][g] */
__device__ int   g_flags[4];                   /* 0: edge is64, 1: sp is64, 2: bool width */

/* ---------------- dtype probe (deterministic, data-derived) ------------- */
__global__ void probe_kernel(const int* edge, const int* sp, const u8* leaf) {
    if (threadIdx.x == 0) {
        /* edge_index[0][1] == 2 (int32 view idx1 = 2) vs int64 (view idx1 = hi word = 0) */
        g_flags[0] = (edge[1] == 0) ? 1 : 0;
        /* sp_ids[1] == 1 (int32) vs 0 (int64 hi word) */
        g_flags[1] = (sp[1] == 0) ? 1 : 0;
        /* leaf_mask[1] and [2] are true; find byte stride of the bool array */
        int bw = leaf[1] ? 1 : (leaf[4] ? 4 : 8);
        g_flags[2] = bw;
    }
}

/* ---------------- kernel 1: per-tree GIN + species pooling -------------- */
__global__ void __launch_bounds__(256, 1)
gin_kernel(const int* __restrict__ edge, const int* __restrict__ sp,
           const u8* __restrict__ leaf, const float* __restrict__ emb,
           const float* __restrict__ W1, const float* __restrict__ b1,
           const float* __restrict__ W2, const float* __restrict__ b2,
           const float* __restrict__ eps, const float* __restrict__ gam,
           const float* __restrict__ bet)
{
    extern __shared__ float sm[];
    float* bufA = sm;                 /* NN*RS floats */
    float* bufB = sm + NN*RS;

    const int g   = blockIdx.x;
    const int tid = threadIdx.x;
    const int em   = g_flags[0] ? 2 : 1;   /* int stride multiplier */
    const int smul = g_flags[1] ? 2 : 1;
    const int bw   = g_flags[2];

    /* species embedding lookup */
    for (int i = tid; i < NN*DD; i += 256) {
        int n = i >> 6, d = i & 63;
        int spv = sp[(size_t)smul * ((size_t)g*NN + n)];
        int eid = (spv < 0) ? NSP : spv;
        bufA[n*RS + d] = emb[eid*DD + d];
    }
    __syncthreads();

    float* cur = bufA; float* oth = bufB;

    for (int l = 0; l < NL; l++) {
        /* zero message buffer */
        for (int i = tid; i < NN*RS; i += 256) oth[i] = 0.f;
        __syncthreads();

        const float e1 = 1.f + eps[l];

        /* message passing: both directions from the first edge half */
        for (int i = tid; i < EPT*DD; i += 256) {
            int e = i >> 6, d = i & 63;
            size_t j = (size_t)g*EPT + e;
            int c = edge[(size_t)em * j];
            int p = edge[(size_t)em * ((size_t)ECOLS + j)];
            int cl = c - g*NN, pl = p - g*NN;
            atomicAdd(&oth[pl*RS + d], cur[cl*RS + d]);
            atomicAdd(&oth[cl*RS + d], cur[pl*RS + d]);
        }
        __syncthreads();

        const float* W1l = W1 + l*DD*DD;
        const float* W2l = W2 + l*DD*DD;
        const float* b1l = b1 + l*DD;
        const float* b2l = b2 + l*DD;
        const float* gl  = gam + l*DD;
        const float* bl  = bet + l*DD;

        /* per-node MLP + residual + LayerNorm (node per thread) */
        for (int n = tid; n < NN; n += 256) {
            float* crow = cur + n*RS;
            float* orow = oth + n*RS;

            float t[DD];
            #pragma unroll
            for (int j = 0; j < 16; j++) {
                float4 bb = ((const float4*)b1l)[j];
                t[4*j] = bb.x; t[4*j+1] = bb.y; t[4*j+2] = bb.z; t[4*j+3] = bb.w;
            }
            for (int k = 0; k < DD; k++) {
                float hk = fmaf(e1, crow[k], orow[k]);      /* (1+eps)x + msg */
                const float4* wr = (const float4*)(W1l + k*DD);
                #pragma unroll
                for (int j = 0; j < 16; j++) {
                    float4 w = wr[j];
                    t[4*j]   = fmaf(hk, w.x, t[4*j]);
                    t[4*j+1] = fmaf(hk, w.y, t[4*j+1]);
                    t[4*j+2] = fmaf(hk, w.z, t[4*j+2]);
                    t[4*j+3] = fmaf(hk, w.w, t[4*j+3]);
                }
            }
            /* relu -> stash in own msg row (done reading it) */
            #pragma unroll
            for (int c = 0; c < DD; c++) orow[c] = fmaxf(t[c], 0.f);

            float y[DD];
            #pragma unroll
            for (int j = 0; j < 16; j++) {
                float4 bb = ((const float4*)b2l)[j];
                y[4*j]   = bb.x + crow[4*j];
                y[4*j+1] = bb.y + crow[4*j+1];
                y[4*j+2] = bb.z + crow[4*j+2];
                y[4*j+3] = bb.w + crow[4*j+3];
            }
            for (int k = 0; k < DD; k++) {
                float tk = orow[k];
                const float4* wr = (const float4*)(W2l + k*DD);
                #pragma unroll
                for (int j = 0; j < 16; j++) {
                    float4 w = wr[j];
                    y[4*j]   = fmaf(tk, w.x, y[4*j]);
                    y[4*j+1] = fmaf(tk, w.y, y[4*j+1]);
                    y[4*j+2] = fmaf(tk, w.z, y[4*j+2]);
                    y[4*j+3] = fmaf(tk, w.w, y[4*j+3]);
                }
            }
            /* LayerNorm (two-pass, register-resident) */
            float mu = 0.f;
            #pragma unroll
            for (int c = 0; c < DD; c++) mu += y[c];
            mu *= (1.f/DD);
            float va = 0.f;
            #pragma unroll
            for (int c = 0; c < DD; c++) { float dv = y[c]-mu; va = fmaf(dv,dv,va); }
            va *= (1.f/DD);
            float rsc = rsqrtf(va + 1e-5f);
            #pragma unroll
            for (int c = 0; c < DD; c++)
                orow[c] = (y[c]-mu)*rsc*gl[c] + bl[c];
        }
        __syncthreads();
        float* tmp = cur; cur = oth; oth = tmp;
    }

    /* species pooling (generic segment mean inside the CTA) */
    float* sums = oth;                  /* NSP*DD */
    float* cnts = oth + NSP*DD;         /* NSP    */
    for (int i = tid; i < NSP*DD + NSP; i += 256) oth[i] = 0.f;
    __syncthreads();
    for (int i = tid; i < NN*DD; i += 256) {
        int n = i >> 6, d = i & 63;
        size_t gi = (size_t)g*NN + n;
        int spv = sp[(size_t)smul * gi];
        if (spv >= 0 && leaf[gi * (size_t)bw] != 0) {
            atomicAdd(&sums[spv*DD + d], cur[n*RS + d]);
            if (d == 0) atomicAdd(&cnts[spv], 1.f);
        }
    }
    __syncthreads();
    for (int i = tid; i < NSP*DD; i += 256) {
        int s = i >> 6, d = i & 63;
        float c = cnts[s];
        g_pool[(size_t)s*NGT*DD + (size_t)g*DD + d] = sums[i] / fmaxf(c, 1.f);
        if (d == 0) g_valid[s*NGT + g] = (c > 0.f) ? 1.f : 0.f;
    }
}

/* ---------------- kernel 2: per-edge clade mean/std ---------------------- */
struct K2Smem {
    float m[NGT*DD];     /* gt_means*has for this edge: 131072 B */
    float minv[NGT];     /* has(g) ? 1/ccnt : 0 */
    float meanb[DD];
    float red[256];
    int   list[NSP];
    int   cnt;
    float nvf;
};

__global__ void __launch_bounds__(256, 1)
clade_kernel(const u8* __restrict__ clade, float* __restrict__ out)
{
    extern __shared__ char smraw[];
    K2Smem* S = (K2Smem*)smraw;
    const int e   = blockIdx.x;
    const int tid = threadIdx.x;
    const int bw  = g_flags[2];

    if (tid == 0) { S->cnt = 0; S->nvf = 0.f; }
    __syncthreads();
    for (int s = tid; s < NSP; s += 256)
        if (clade[((size_t)e*NSP + s) * (size_t)bw] != 0) {
            int p = atomicAdd(&S->cnt, 1);
            S->list[p] = s;
        }
    __syncthreads();
    const int nsp = S->cnt;

    /* ccnt / has / n_v */
    for (int gg = tid; gg < NGT; gg += 256) {
        float c = 0.f;
        for (int j = 0; j < nsp; j++) c += g_valid[S->list[j]*NGT + gg];
        S->minv[gg] = (c > 0.f) ? (1.f/c) : 0.f;
        if (c > 0.f) atomicAdd(&S->nvf, 1.f);
    }
    __syncthreads();
    const float n_v = S->nvf;

    /* csum over clade species, register float4 accumulators, then /ccnt */
    for (int gc = 0; gc < 8; gc++) {
        float4 acc[4];
        #pragma unroll
        for (int r = 0; r < 4; r++) acc[r] = make_float4(0.f,0.f,0.f,0.f);
        for (int j = 0; j < nsp; j++) {
            int s = S->list[j];
            const float4* src = (const float4*)(g_pool + (size_t)s*NGT*DD + gc*4096);
            #pragma unroll
            for (int r = 0; r < 4; r++) {
                float4 v = src[tid + r*256];
                acc[r].x += v.x; acc[r].y += v.y; acc[r].z += v.z; acc[r].w += v.w;
            }
        }
        #pragma unroll
        for (int r = 0; r < 4; r++) {
            int q4 = tid + r*256;
            float iv = S->minv[gc*64 + (q4 >> 4)];
            float4 v; v.x = acc[r].x*iv; v.y = acc[r].y*iv; v.z = acc[r].z*iv; v.w = acc[r].w*iv;
            ((float4*)S->m)[gc*1024 + q4] = v;
        }
    }
    __syncthreads();

    const int d = tid & 63, part = tid >> 6;

    /* mean over gene trees */
    float s1 = 0.f;
    for (int gg = part*128; gg < part*128 + 128; gg++) s1 += S->m[gg*64 + d];
    S->red[tid] = s1;
    __syncthreads();
    if (tid < 64) {
        float tot = S->red[d] + S->red[64+d] + S->red[128+d] + S->red[192+d];
        float mn = tot / fmaxf(n_v, 1.f);     /* n_v==0 -> tot==0 -> 0 */
        S->meanb[d] = mn;
        out[(size_t)e*2*DD + d] = mn;
    }
    __syncthreads();

    /* unbiased std (two-pass, exact) */
    float mn = S->meanb[d];
    float s2 = 0.f;
    for (int gg = part*128; gg < part*128 + 128; gg++) {
        if (S->minv[gg] > 0.f) { float dv = S->m[gg*64 + d] - mn; s2 = fmaf(dv, dv, s2); }
    }
    S->red[tid] = s2;
    __syncthreads();
    if (tid < 64) {
        float tot = S->red[d] + S->red[64+d] + S->red[128+d] + S->red[192+d];
        float var = tot / fmaxf(n_v - 1.f, 1.f);
        out[(size_t)e*2*DD + DD + d] = (n_v > 1.f) ? sqrtf(var) : 0.f;
    }
}

/* ---------------- host launch ------------------------------------------- */
extern "C" void kernel_launch(void* const* d_in, const int* in_sizes, int n_in,
                              void* d_out, int out_size)
{
    /* n_gt (scalar) may or may not be input 5; emb_table has (NSP+1)*DD elems */
    int o = (n_in > 5 && in_sizes[5] == (NSP+1)*DD) ? 0 : 1;

    const int* edge = (const int*)d_in[0];
    const int* sp   = (const int*)d_in[1];
    const u8*  leaf = (const u8*)d_in[2];
    const u8*  clad = (const u8*)d_in[4];
    const float* emb = (const float*)d_in[5+o];
    const float* W1  = (const float*)d_in[6+o];
    const float* b1  = (const float*)d_in[7+o];
    const float* W2  = (const float*)d_in[8+o];
    const float* b2  = (const float*)d_in[9+o];
    const float* eps = (const float*)d_in[10+o];
    const float* gam = (const float*)d_in[11+o];
    const float* bet = (const float*)d_in[12+o];

    const int smem1 = 2*NN*RS*(int)sizeof(float);     /* 207480 B */
    const int smem2 = (int)sizeof(K2Smem);            /* ~135 KB  */
    cudaFuncSetAttribute(gin_kernel,   cudaFuncAttributeMaxDynamicSharedMemorySize, smem1);
    cudaFuncSetAttribute(clade_kernel, cudaFuncAttributeMaxDynamicSharedMemorySize, smem2);

    probe_kernel<<<1, 1>>>(edge, sp, leaf);
    gin_kernel<<<NGT, 256, smem1>>>(edge, sp, leaf, emb, W1, b1, W2, b2, eps, gam, bet);
    clade_kernel<<<NED, 256, smem2>>>(clad, (float*)d_out);
    (void)out_size; (void)n_in;
}

// round 2
// speedup vs baseline: 2.8816x; 2.8816x over previous
#include <cuda_runtime.h>

#define NGT 512
#define NN  399
#define NSP 200
#define NED 397
#define DD  64
#define EPT 398
#define ECOLS (NGT*EPT*2)
#define RS  65
#define RSA 25936              /* 16B-aligned buffer stride (floats) */
#define EG  16                 /* edges per gemm CTA */
#define NEG 25                 /* edge groups (covers 400 >= 397) */

typedef unsigned char u8;
typedef unsigned long long ull;

/* ---------------- scratch (static device globals) ----------------------- */
__device__ float g_pool[(size_t)NSP*NGT*DD];     /* [s][g][d] 26 MB */
__device__ float g_valid[NSP*NGT];               /* [s][g] */
__device__ float g_gt[(size_t)EG*NEG*NGT*DD];    /* [e][g][d] 52 MB */
__device__ float g_minv[EG*NEG*NGT];             /* [e][g] */
__device__ float g_nv[EG*NEG];

/* ---------------- f32x2 helpers (sm_100+) -------------------------------- */
__device__ __forceinline__ ull pk2(float x){ ull r; asm("mov.b64 %0,{%1,%1};" : "=l"(r) : "f"(x)); return r; }
__device__ __forceinline__ ull pk(float a, float b){ ull r; asm("mov.b64 %0,{%1,%2};" : "=l"(r) : "f"(a), "f"(b)); return r; }
__device__ __forceinline__ float2 up2(ull v){ float2 f; asm("mov.b64 {%0,%1},%2;" : "=f"(f.x), "=f"(f.y) : "l"(v)); return f; }
__device__ __forceinline__ void fma2(ull &d, ull a, ull b){ asm("fma.rn.f32x2 %0,%1,%2,%0;" : "+l"(d) : "l"(a), "l"(b)); }

/* ======================= kernel 1: GIN per tree ========================== */
__global__ void __launch_bounds__(512, 1)
gin_kernel(const int* __restrict__ edge, const int* __restrict__ sp,
           const u8* __restrict__ leaf, const float* __restrict__ emb,
           const float* __restrict__ W1, const float* __restrict__ b1,
           const float* __restrict__ W2, const float* __restrict__ b2,
           const float* __restrict__ eps, const float* __restrict__ gam,
           const float* __restrict__ bet)
{
    extern __shared__ float smf[];
    float* xb   = smf;                 /* x buffer, rows stride RS       */
    float* hb   = smf + RSA;           /* h / relu buffer                */
    float* wb   = smf + 2*RSA;         /* 2048: staged half-W            */
    float* vec  = wb + 2048;           /* 256: b1|b2|gamma|beta          */
    int*   ipar = (int*)(vec + 256);   /* 400 */
    int*   ioff = ipar + 400;          /* 401: child counts -> offsets   */
    int*   ilist= ioff + 401;          /* 400 */
    int*   soff = ilist + 400;         /* 204: species counts -> offsets */
    int*   slist= soff + 204;          /* 400 */
    short* ssp  = (short*)(slist + 400);  /* 400 */
    u8*    slf  = (u8*)(ssp + 400);       /* 400 */

    const int tid = threadIdx.x;
    const int g   = blockIdx.x;
    /* dtype width probes (deterministic, data-derived, per-CTA) */
    const int em  = (edge[1] == 0) ? 2 : 1;
    const int smu = (sp[1]   == 0) ? 2 : 1;
    const int bw  = leaf[1] ? 1 : (leaf[4] ? 4 : 8);

    /* stage species / leaf flags; zero counts */
    for (int n = tid; n < NN; n += 512) {
        size_t gi = (size_t)g*NN + n;
        int s = sp[(size_t)smu * gi];
        ssp[n] = (short)s;
        slf[n] = (s >= 0 && leaf[gi * (size_t)bw] != 0) ? 1 : 0;
    }
    for (int n = tid; n <= NN;  n += 512) ioff[n] = 0;
    for (int s = tid; s <= NSP; s += 512) soff[s] = 0;
    __syncthreads();

    /* species embedding */
    for (int i = tid; i < NN*DD; i += 512) {
        int n = i >> 6, d = i & 63;
        int s = ssp[n];
        xb[n*RS + d] = emb[(s < 0 ? NSP : s)*DD + d];
    }
    /* parents + child counts (int atomics -> deterministic counts) */
    for (int e = tid; e < EPT; e += 512) {
        int p = edge[(size_t)em * ((size_t)ECOLS + (size_t)g*EPT + e)] - g*NN;
        ipar[e+1] = p;
        atomicAdd(&ioff[p], 1);
    }
    if (tid == 0) ipar[0] = 0;
    for (int n = tid; n < NN; n += 512)
        if (slf[n]) atomicAdd(&soff[ssp[n]], 1);
    __syncthreads();

    /* exclusive scans (warp 0: children, warp 1: species) */
    const int lane = tid & 31, wrp = tid >> 5;
    if (wrp == 0) {
        int carry = 0;
        for (int base = 0; base < NN; base += 32) {
            int idx = base + lane;
            int orig = (idx < NN) ? ioff[idx] : 0;
            int v = orig;
            #pragma unroll
            for (int o = 1; o < 32; o <<= 1) { int t = __shfl_up_sync(0xffffffffu, v, o); if (lane >= o) v += t; }
            if (idx < NN) ioff[idx] = carry + v - orig;
            carry += __shfl_sync(0xffffffffu, v, 31);
        }
        if (lane == 0) ioff[NN] = carry;
    } else if (wrp == 1) {
        int carry = 0;
        for (int base = 0; base < NSP; base += 32) {
            int idx = base + lane;
            int orig = (idx < NSP) ? soff[idx] : 0;
            int v = orig;
            #pragma unroll
            for (int o = 1; o < 32; o <<= 1) { int t = __shfl_up_sync(0xffffffffu, v, o); if (lane >= o) v += t; }
            if (idx < NSP) soff[idx] = carry + v - orig;
            carry += __shfl_sync(0xffffffffu, v, 31);
        }
        if (lane == 0) soff[NSP] = carry;
    }
    __syncthreads();

    /* deterministic CSR fill via rank counting (no ordering races) */
    for (int c = 1 + tid; c < NN; c += 512) {
        int p = ipar[c], r = 0;
        for (int c2 = 1; c2 < c; c2++) r += (ipar[c2] == p);
        ilist[ioff[p] + r] = c;
    }
    for (int n = tid; n < NN; n += 512) {
        if (slf[n]) {
            int s = ssp[n], r = 0;
            for (int n2 = 0; n2 < n; n2++) r += (slf[n2] && ssp[n2] == s);
            slist[soff[s] + r] = n;
        }
    }
    __syncthreads();

    /* ------------------------- 2 GIN layers ------------------------- */
    ull acc[32];
    for (int l = 0; l < 2; l++) {
        const float* W1l = W1 + l*DD*DD;
        const float* W2l = W2 + l*DD*DD;
        if (tid < 64) {
            vec[tid]       = b1[l*DD + tid];
            vec[64 + tid]  = b2[l*DD + tid];
            vec[128 + tid] = gam[l*DD + tid];
            vec[192 + tid] = bet[l*DD + tid];
        }
        const float e1 = 1.f + eps[l];
        __syncthreads();

        /* gather: h = (1+eps)x + x[parent] + sum_children x  (no atomics) */
        for (int i = tid; i < NN*DD; i += 512) {
            int n = i >> 6, d = i & 63;
            float a = e1 * xb[n*RS + d];
            if (n > 0) a += xb[ipar[n]*RS + d];
            int o1 = ioff[n+1];
            for (int j = ioff[n]; j < o1; j++) a += xb[ilist[j]*RS + d];
            hb[n*RS + d] = a;
        }

        /* matmul1: t = h @ W1 + b1  (FFMA2, W staged in smem) */
        #pragma unroll
        for (int j = 0; j < 32; j++) acc[j] = ((const ull*)vec)[j];
        for (int ch = 0; ch < 2; ch++) {
            __syncthreads();
            for (int i = tid; i < 2048; i += 512) wb[i] = W1l[ch*2048 + i];
            __syncthreads();
            if (tid < NN) {
                for (int k = 0; k < 32; k++) {
                    ull hk = pk2(hb[tid*RS + ch*32 + k]);
                    const ulonglong2* wr = (const ulonglong2*)(wb + k*DD);
                    #pragma unroll
                    for (int j = 0; j < 16; j++) {
                        ulonglong2 w = wr[j];
                        fma2(acc[2*j],   hk, w.x);
                        fma2(acc[2*j+1], hk, w.y);
                    }
                }
            }
        }
        /* relu -> hb (own row only; no cross-thread readers) */
        if (tid < NN) {
            #pragma unroll
            for (int j = 0; j < 32; j++) {
                float2 f = up2(acc[j]);
                hb[tid*RS + 2*j]   = fmaxf(f.x, 0.f);
                hb[tid*RS + 2*j+1] = fmaxf(f.y, 0.f);
            }
            /* matmul2 acc init: b2 + residual x */
            #pragma unroll
            for (int j = 0; j < 32; j++)
                acc[j] = pk(vec[64 + 2*j]   + xb[tid*RS + 2*j],
                            vec[64 + 2*j+1] + xb[tid*RS + 2*j+1]);
        }
        for (int ch = 0; ch < 2; ch++) {
            __syncthreads();
            for (int i = tid; i < 2048; i += 512) wb[i] = W2l[ch*2048 + i];
            __syncthreads();
            if (tid < NN) {
                for (int k = 0; k < 32; k++) {
                    ull hk = pk2(hb[tid*RS + ch*32 + k]);
                    const ulonglong2* wr = (const ulonglong2*)(wb + k*DD);
                    #pragma unroll
                    for (int j = 0; j < 16; j++) {
                        ulonglong2 w = wr[j];
                        fma2(acc[2*j],   hk, w.x);
                        fma2(acc[2*j+1], hk, w.y);
                    }
                }
            }
        }
        /* LayerNorm in registers, write new x */
        if (tid < NN) {
            float mu = 0.f;
            #pragma unroll
            for (int j = 0; j < 32; j++) { float2 f = up2(acc[j]); mu += f.x + f.y; }
            mu *= (1.f/DD);
            float va = 0.f;
            #pragma unroll
            for (int j = 0; j < 32; j++) {
                float2 f = up2(acc[j]);
                float dx = f.x - mu, dy = f.y - mu;
                va = fmaf(dx, dx, va); va = fmaf(dy, dy, va);
            }
            va *= (1.f/DD);
            float rsc = rsqrtf(va + 1e-5f);
            #pragma unroll
            for (int j = 0; j < 32; j++) {
                float2 f = up2(acc[j]);
                xb[tid*RS + 2*j]   = (f.x - mu)*rsc*vec[128 + 2*j]   + vec[192 + 2*j];
                xb[tid*RS + 2*j+1] = (f.y - mu)*rsc*vec[128 + 2*j+1] + vec[192 + 2*j+1];
            }
        }
        __syncthreads();
    }

    /* species pooling via CSR gather (no atomics) */
    for (int i = tid; i < NSP*DD; i += 512) {
        int s = i >> 6, d = i & 63;
        int o0 = soff[s], o1 = soff[s+1];
        float a = 0.f;
        for (int j = o0; j < o1; j++) a += xb[slist[j]*RS + d];
        float c = (float)(o1 - o0);
        g_pool[(size_t)s*NGT*DD + (size_t)g*DD + d] = a / fmaxf(c, 1.f);
        if (d == 0) g_valid[s*NGT + g] = (c > 0.f) ? 1.f : 0.f;
    }
}

/* =============== kernel 2: per-(edge,tree) valid counts ================== */
__global__ void __launch_bounds__(256, 4)
cnt_kernel(const u8* __restrict__ clade, const u8* __restrict__ leaf)
{
    __shared__ float msk[NSP];
    __shared__ int nv;
    const int e = blockIdx.x, tid = threadIdx.x;
    const int bw = leaf[1] ? 1 : (leaf[4] ? 4 : 8);
    if (tid == 0) nv = 0;
    for (int s = tid; s < NSP; s += 256)
        msk[s] = clade[((size_t)e*NSP + s) * (size_t)bw] ? 1.f : 0.f;
    __syncthreads();
    for (int gg = tid; gg < NGT; gg += 256) {
        float c = 0.f;
        for (int s = 0; s < NSP; s++)
            if (msk[s] != 0.f) c += g_valid[s*NGT + gg];
        g_minv[e*NGT + gg] = (c > 0.f) ? (1.f/c) : 0.f;
        if (c > 0.f) atomicAdd(&nv, 1);
    }
    __syncthreads();
    if (tid == 0) g_nv[e] = (float)nv;
}

/* ======= kernel 3: masked GEMM -> gt_means[e][g][d] (16 edges/CTA) ======= */
__global__ void __launch_bounds__(256, 2)
gemm_kernel(const u8* __restrict__ clade, const u8* __restrict__ leaf)
{
    __shared__ ull  msk[NSP*EG];      /* packed (m,m) per (s,e) */
    __shared__ float minv_s[EG*16];   /* [e][g_local] */
    const int tid = threadIdx.x;
    const int ct  = blockIdx.x;       /* column tile: 1024 cols  */
    const int eg  = blockIdx.y;       /* edge group of 16        */
    const int bw  = leaf[1] ? 1 : (leaf[4] ? 4 : 8);

    for (int i = tid; i < NSP*EG; i += 256) {
        int s = i / EG, e_ = i % EG;
        int ee = eg*EG + e_;
        float mv = (ee < NED && clade[((size_t)ee*NSP + s)*(size_t)bw]) ? 1.f : 0.f;
        msk[s*EG + e_] = pk2(mv);
    }
    for (int i = tid; i < EG*16; i += 256) {
        int e_ = i >> 4, gl = i & 15;
        int ee = eg*EG + e_;
        minv_s[i] = (ee < NED) ? g_minv[ee*NGT + ct*16 + gl] : 0.f;
    }
    __syncthreads();

    const int col = ct*1024 + tid*4;
    ull a[EG][2];
    #pragma unroll
    for (int e_ = 0; e_ < EG; e_++) { a[e_][0] = 0ull; a[e_][1] = 0ull; }

    for (int s = 0; s < NSP; s++) {
        float4 v = *(const float4*)(g_pool + (size_t)s*NGT*DD + col);
        ull v01 = pk(v.x, v.y), v23 = pk(v.z, v.w);
        const ull* ms = msk + s*EG;
        #pragma unroll
        for (int e_ = 0; e_ < EG; e_++) {
            ull mk = ms[e_];
            fma2(a[e_][0], mk, v01);
            fma2(a[e_][1], mk, v23);
        }
    }

    const int gl = tid >> 4;   /* g within 16-g tile (col>>6 - ct*16) */
    #pragma unroll
    for (int e_ = 0; e_ < EG; e_++) {
        int ee = eg*EG + e_;
        if (ee < NED) {
            float iv = minv_s[e_*16 + gl];
            float2 f0 = up2(a[e_][0]), f1 = up2(a[e_][1]);
            float4 o; o.x = f0.x*iv; o.y = f0.y*iv; o.z = f1.x*iv; o.w = f1.y*iv;
            *(float4*)(g_gt + (size_t)ee*NGT*DD + col) = o;
        }
    }
}

/* ================= kernel 4: per-edge mean / unbiased std ================ */
__global__ void __launch_bounds__(256, 4)
stats_kernel(float* __restrict__ out)
{
    __shared__ float red[256];
    __shared__ float meanb[DD];
    const int e = blockIdx.x, tid = threadIdx.x;
    const int d = tid & 63, part = tid >> 6;
    const float nv = g_nv[e];
    const float* gt = g_gt + (size_t)e*NGT*DD;

    float s1 = 0.f;
    for (int gg = part*128; gg < part*128 + 128; gg++) s1 += gt[gg*DD + d];
    red[tid] = s1;
    __syncthreads();
    if (tid < 64) {
        float tot = red[d] + red[64+d] + red[128+d] + red[192+d];
        float mn = tot / fmaxf(nv, 1.f);
        meanb[d] = mn;
        out[(size_t)e*2*DD + d] = mn;
    }
    __syncthreads();
    float mn = meanb[d];
    float s2 = 0.f;
    for (int gg = part*128; gg < part*128 + 128; gg++) {
        if (g_minv[e*NGT + gg] > 0.f) {
            float dv = gt[gg*DD + d] - mn;
            s2 = fmaf(dv, dv, s2);
        }
    }
    red[tid] = s2;
    __syncthreads();
    if (tid < 64) {
        float tot = red[d] + red[64+d] + red[128+d] + red[192+d];
        float var = tot / fmaxf(nv - 1.f, 1.f);
        out[(size_t)e*2*DD + DD + d] = (nv > 1.f) ? sqrtf(var) : 0.f;
    }
}

/* ------------------------------ host -------------------------------------*/
extern "C" void kernel_launch(void* const* d_in, const int* in_sizes, int n_in,
                              void* d_out, int out_size)
{
    /* n_gt (scalar) may or may not be input 5; emb_table has (NSP+1)*DD elems */
    int o = (n_in > 5 && in_sizes[5] == (NSP+1)*DD) ? 0 : 1;

    const int* edge = (const int*)d_in[0];
    const int* sp   = (const int*)d_in[1];
    const u8*  leaf = (const u8*)d_in[2];
    const u8*  clad = (const u8*)d_in[4];
    const float* emb = (const float*)d_in[5+o];
    const float* W1  = (const float*)d_in[6+o];
    const float* b1  = (const float*)d_in[7+o];
    const float* W2  = (const float*)d_in[8+o];
    const float* b2  = (const float*)d_in[9+o];
    const float* eps = (const float*)d_in[10+o];
    const float* gam = (const float*)d_in[11+o];
    const float* bet = (const float*)d_in[12+o];

    const int smem1 = (2*RSA + 2048 + 256)*4 + (400+401+400+204+400)*4 + 400*2 + 400;
    cudaFuncSetAttribute(gin_kernel, cudaFuncAttributeMaxDynamicSharedMemorySize, smem1);

    gin_kernel<<<NGT, 512, smem1>>>(edge, sp, leaf, emb, W1, b1, W2, b2, eps, gam, bet);
    cnt_kernel<<<NED, 256>>>(clad, leaf);
    gemm_kernel<<<dim3(32, NEG), 256>>>(clad, leaf);
    stats_kernel<<<NED, 256>>>((float*)d_out);
    (void)out_size; (void)n_in; (void)in_sizes;
}

// round 5
// speedup vs baseline: 3.3309x; 1.1559x over previous
#include <cuda_runtime.h>
#include <cuda_bf16.h>
#include <cstdint>

#define NGT 512
#define NN  399
#define NSP 200
#define NED 397
#define DD  64
#define EPT 398
#define ECOLS (NGT*EPT*2)
#define RS  65
#define RSA 25936              /* 16B-aligned buffer stride (floats) */
#define GTS (NGT*DD)           /* 32768: g_gt row stride */
#define KPAD 256
#define EPAD 512

typedef unsigned char u8;
typedef unsigned long long ull;
typedef unsigned int u32;
typedef unsigned short u16;

/* ---------------- scratch (static device globals, zero-init) ------------ */
__device__ __nv_bfloat16 g_pool_bf[(size_t)NSP*NGT*DD];   /* [s][g][d] 13MB */
__device__ __nv_bfloat16 g_poolT[(size_t)GTS*KPAD];       /* [gd][s] 16.8MB */
__device__ __nv_bfloat16 g_maskA[(size_t)EPAD*KPAD];      /* [e][s] */
__device__ float g_valid[NSP*NGT];                        /* [s][g] */
__device__ float g_gt[(size_t)400*GTS];                   /* [e][g][d] 52MB */
__device__ float g_minv[(size_t)EPAD*NGT];                /* [e][g] */
__device__ float g_nv[EPAD];

/* ---------------- f32x2 helpers ------------------------------------------ */
__device__ __forceinline__ ull pk2(float x){ ull r; asm("mov.b64 %0,{%1,%1};" : "=l"(r) : "f"(x)); return r; }
__device__ __forceinline__ ull pk(float a, float b){ ull r; asm("mov.b64 %0,{%1,%2};" : "=l"(r) : "f"(a), "f"(b)); return r; }
__device__ __forceinline__ float2 up2(ull v){ float2 f; asm("mov.b64 {%0,%1},%2;" : "=f"(f.x), "=f"(f.y) : "l"(v)); return f; }
__device__ __forceinline__ void fma2(ull &d, ull a, ull b){ asm("fma.rn.f32x2 %0,%1,%2,%0;" : "+l"(d) : "l"(a), "l"(b)); }

__device__ __forceinline__ u32 smem_u32(const void* p){
    u32 a; asm("{ .reg .u64 t; cvta.to.shared.u64 t, %1; cvt.u32.u64 %0, t; }" : "=r"(a) : "l"(p));
    return a;
}
#define LDSM_X4(r0,r1,r2,r3,addr) \
    asm volatile("ldmatrix.sync.aligned.m8n8.x4.shared.b16 {%0,%1,%2,%3}, [%4];" \
        : "=r"(r0), "=r"(r1), "=r"(r2), "=r"(r3) : "r"(addr))
#define MMA_BF16(c0,c1,c2,c3,a0,a1,a2,a3,b0,b1) \
    asm volatile("mma.sync.aligned.m16n8k16.row.col.f32.bf16.bf16.f32 " \
        "{%0,%1,%2,%3},{%4,%5,%6,%7},{%8,%9},{%0,%1,%2,%3};" \
        : "+f"(c0), "+f"(c1), "+f"(c2), "+f"(c3) \
        : "r"(a0), "r"(a1), "r"(a2), "r"(a3), "r"(b0), "r"(b1))

/* ======================= kernel 1: GIN per tree ========================== */
__global__ void __launch_bounds__(512, 1)
gin_kernel(const int* __restrict__ edge, const int* __restrict__ sp,
           const u8* __restrict__ leaf, const float* __restrict__ emb,
           const float* __restrict__ W1, const float* __restrict__ b1,
           const float* __restrict__ W2, const float* __restrict__ b2,
           const float* __restrict__ eps, const float* __restrict__ gam,
           const float* __restrict__ bet)
{
    extern __shared__ float smf[];
    float* xb   = smf;
    float* hb   = smf + RSA;
    float* wb   = smf + 2*RSA;
    float* vec  = wb + 2048;
    int*   ipar = (int*)(vec + 256);
    int*   ioff = ipar + 400;
    int*   ilist= ioff + 401;
    int*   soff = ilist + 400;
    int*   slist= soff + 204;
    short* ssp  = (short*)(slist + 400);
    u8*    slf  = (u8*)(ssp + 400);

    const int tid = threadIdx.x;
    const int g   = blockIdx.x;
    const int em  = (edge[1] == 0) ? 2 : 1;
    const int smu = (sp[1]   == 0) ? 2 : 1;
    const int bw  = leaf[1] ? 1 : (leaf[4] ? 4 : 8);

    for (int n = tid; n < NN; n += 512) {
        size_t gi = (size_t)g*NN + n;
        int s = sp[(size_t)smu * gi];
        ssp[n] = (short)s;
        slf[n] = (s >= 0 && leaf[gi * (size_t)bw] != 0) ? 1 : 0;
    }
    for (int n = tid; n <= NN;  n += 512) ioff[n] = 0;
    for (int s = tid; s <= NSP; s += 512) soff[s] = 0;
    __syncthreads();

    for (int i = tid; i < NN*DD; i += 512) {
        int n = i >> 6, d = i & 63;
        int s = ssp[n];
        xb[n*RS + d] = emb[(s < 0 ? NSP : s)*DD + d];
    }
    for (int e = tid; e < EPT; e += 512) {
        int p = edge[(size_t)em * ((size_t)ECOLS + (size_t)g*EPT + e)] - g*NN;
        ipar[e+1] = p;
        atomicAdd(&ioff[p], 1);
    }
    if (tid == 0) ipar[0] = 0;
    for (int n = tid; n < NN; n += 512)
        if (slf[n]) atomicAdd(&soff[ssp[n]], 1);
    __syncthreads();

    const int lane = tid & 31, wrp = tid >> 5;
    if (wrp == 0) {
        int carry = 0;
        for (int base = 0; base < NN; base += 32) {
            int idx = base + lane;
            int orig = (idx < NN) ? ioff[idx] : 0;
            int v = orig;
            #pragma unroll
            for (int o = 1; o < 32; o <<= 1) { int t = __shfl_up_sync(0xffffffffu, v, o); if (lane >= o) v += t; }
            if (idx < NN) ioff[idx] = carry + v - orig;
            carry += __shfl_sync(0xffffffffu, v, 31);
        }
        if (lane == 0) ioff[NN] = carry;
    } else if (wrp == 1) {
        int carry = 0;
        for (int base = 0; base < NSP; base += 32) {
            int idx = base + lane;
            int orig = (idx < NSP) ? soff[idx] : 0;
            int v = orig;
            #pragma unroll
            for (int o = 1; o < 32; o <<= 1) { int t = __shfl_up_sync(0xffffffffu, v, o); if (lane >= o) v += t; }
            if (idx < NSP) soff[idx] = carry + v - orig;
            carry += __shfl_sync(0xffffffffu, v, 31);
        }
        if (lane == 0) soff[NSP] = carry;
    }
    __syncthreads();

    for (int c = 1 + tid; c < NN; c += 512) {
        int p = ipar[c], r = 0;
        for (int c2 = 1; c2 < c; c2++) r += (ipar[c2] == p);
        ilist[ioff[p] + r] = c;
    }
    for (int n = tid; n < NN; n += 512) {
        if (slf[n]) {
            int s = ssp[n], r = 0;
            for (int n2 = 0; n2 < n; n2++) r += (slf[n2] && ssp[n2] == s);
            slist[soff[s] + r] = n;
        }
    }
    __syncthreads();

    ull acc[32];
    for (int l = 0; l < 2; l++) {
        const float* W1l = W1 + l*DD*DD;
        const float* W2l = W2 + l*DD*DD;
        if (tid < 64) {
            vec[tid]       = b1[l*DD + tid];
            vec[64 + tid]  = b2[l*DD + tid];
            vec[128 + tid] = gam[l*DD + tid];
            vec[192 + tid] = bet[l*DD + tid];
        }
        const float e1 = 1.f + eps[l];
        __syncthreads();

        for (int i = tid; i < NN*DD; i += 512) {
            int n = i >> 6, d = i & 63;
            float a = e1 * xb[n*RS + d];
            if (n > 0) a += xb[ipar[n]*RS + d];
            int o1 = ioff[n+1];
            for (int j = ioff[n]; j < o1; j++) a += xb[ilist[j]*RS + d];
            hb[n*RS + d] = a;
        }

        #pragma unroll
        for (int j = 0; j < 32; j++) acc[j] = ((const ull*)vec)[j];
        for (int ch = 0; ch < 2; ch++) {
            __syncthreads();
            for (int i = tid; i < 2048; i += 512) wb[i] = W1l[ch*2048 + i];
            __syncthreads();
            if (tid < NN) {
                for (int k = 0; k < 32; k++) {
                    ull hk = pk2(hb[tid*RS + ch*32 + k]);
                    const ulonglong2* wr = (const ulonglong2*)(wb + k*DD);
                    #pragma unroll
                    for (int j = 0; j < 16; j++) {
                        ulonglong2 w = wr[j];
                        fma2(acc[2*j],   hk, w.x);
                        fma2(acc[2*j+1], hk, w.y);
                    }
                }
            }
        }
        if (tid < NN) {
            #pragma unroll
            for (int j = 0; j < 32; j++) {
                float2 f = up2(acc[j]);
                hb[tid*RS + 2*j]   = fmaxf(f.x, 0.f);
                hb[tid*RS + 2*j+1] = fmaxf(f.y, 0.f);
            }
            #pragma unroll
            for (int j = 0; j < 32; j++)
                acc[j] = pk(vec[64 + 2*j]   + xb[tid*RS + 2*j],
                            vec[64 + 2*j+1] + xb[tid*RS + 2*j+1]);
        }
        for (int ch = 0; ch < 2; ch++) {
            __syncthreads();
            for (int i = tid; i < 2048; i += 512) wb[i] = W2l[ch*2048 + i];
            __syncthreads();
            if (tid < NN) {
                for (int k = 0; k < 32; k++) {
                    ull hk = pk2(hb[tid*RS + ch*32 + k]);
                    const ulonglong2* wr = (const ulonglong2*)(wb + k*DD);
                    #pragma unroll
                    for (int j = 0; j < 16; j++) {
                        ulonglong2 w = wr[j];
                        fma2(acc[2*j],   hk, w.x);
                        fma2(acc[2*j+1], hk, w.y);
                    }
                }
            }
        }
        if (tid < NN) {
            float mu = 0.f;
            #pragma unroll
            for (int j = 0; j < 32; j++) { float2 f = up2(acc[j]); mu += f.x + f.y; }
            mu *= (1.f/DD);
            float va = 0.f;
            #pragma unroll
            for (int j = 0; j < 32; j++) {
                float2 f = up2(acc[j]);
                float dx = f.x - mu, dy = f.y - mu;
                va = fmaf(dx, dx, va); va = fmaf(dy, dy, va);
            }
            va *= (1.f/DD);
            float rsc = rsqrtf(va + 1e-5f);
            #pragma unroll
            for (int j = 0; j < 32; j++) {
                float2 f = up2(acc[j]);
                xb[tid*RS + 2*j]   = (f.x - mu)*rsc*vec[128 + 2*j]   + vec[192 + 2*j];
                xb[tid*RS + 2*j+1] = (f.y - mu)*rsc*vec[128 + 2*j+1] + vec[192 + 2*j+1];
            }
        }
        __syncthreads();
    }

    /* species pooling -> bf16 pool + fp32 valid */
    for (int i = tid; i < NSP*DD; i += 512) {
        int s = i >> 6, d = i & 63;
        int o0 = soff[s], o1 = soff[s+1];
        float a = 0.f;
        for (int j = o0; j < o1; j++) a += xb[slist[j]*RS + d];
        float c = (float)(o1 - o0);
        g_pool_bf[(size_t)s*NGT*DD + (size_t)g*DD + d] = __float2bfloat16(a / fmaxf(c, 1.f));
        if (d == 0) g_valid[s*NGT + g] = (c > 0.f) ? 1.f : 0.f;
    }
}

/* =============== kernel 2: per-(edge,tree) valid counts ================== */
__global__ void __launch_bounds__(256, 4)
cnt_kernel(const u8* __restrict__ clade, const u8* __restrict__ leaf)
{
    __shared__ float msk[NSP];
    __shared__ int nv;
    const int e = blockIdx.x, tid = threadIdx.x;
    const int bw = leaf[1] ? 1 : (leaf[4] ? 4 : 8);
    if (tid == 0) nv = 0;
    for (int s = tid; s < NSP; s += 256)
        msk[s] = clade[((size_t)e*NSP + s) * (size_t)bw] ? 1.f : 0.f;
    __syncthreads();
    for (int gg = tid; gg < NGT; gg += 256) {
        float c = 0.f;
        for (int s = 0; s < NSP; s++)
            if (msk[s] != 0.f) c += g_valid[s*NGT + gg];
        g_minv[(size_t)e*NGT + gg] = (c > 0.f) ? (1.f/c) : 0.f;
        if (c > 0.f) atomicAdd(&nv, 1);
    }
    __syncthreads();
    if (tid == 0) g_nv[e] = (float)nv;
}

/* =============== kernel 2b: build bf16 mask A [EPAD x KPAD] ============= */
__global__ void maskprep_kernel(const u8* __restrict__ clade, const u8* __restrict__ leaf)
{
    const int e = blockIdx.x, s = threadIdx.x;   /* grid EPAD, block KPAD */
    const int bw = leaf[1] ? 1 : (leaf[4] ? 4 : 8);
    float v = 0.f;
    if (e < NED && s < NSP && clade[((size_t)e*NSP + s)*(size_t)bw]) v = 1.f;
    g_maskA[(size_t)e*KPAD + s] = __float2bfloat16(v);
}

/* =============== kernel 2c: transpose pool -> poolT [gd][s] ============= */
__global__ void __launch_bounds__(256)
transpose_kernel()
{
    int t = blockIdx.x*256 + threadIdx.x;     /* grid 4096 */
    int n  = t >> 5;
    int sc = (t & 31) * 8;
    u16 v[8];
    #pragma unroll
    for (int j = 0; j < 8; j++) {
        int s = sc + j;
        v[j] = (s < NSP) ? *(const u16*)&g_pool_bf[(size_t)s*GTS + n] : (u16)0;
    }
    *(uint4*)&g_poolT[(size_t)n*KPAD + sc] = *(uint4*)v;
}

/* ====== kernel 3: mma.sync bf16 GEMM  C[e,gd] = sum_s M[e,s] P[gd,s] ==== */
/* CTA: 256 thr = 8 warps (4 m x 2 n). Tile: 128 edges x 64 cols (1 tree). */
/* A tile loaded once, 4 trees per CTA. smem rows padded to 264 bf16.      */
#define APAD 264
#define SMA_OFF 0
#define SMB_OFF (128*APAD*2)             /* 67584 */
#define SMIV_OFF (SMB_OFF + 64*APAD*2)   /* 101376 */
#define SMG_TOT (SMIV_OFF + 128*4)       /* 101888 */

__global__ void __launch_bounds__(256, 1)
gemm_mma_kernel()
{
    extern __shared__ char smc[];
    const u32 smem = smem_u32(smc);
    __nv_bfloat16* smA = (__nv_bfloat16*)(smc + SMA_OFF);
    __nv_bfloat16* smB = (__nv_bfloat16*)(smc + SMB_OFF);
    float*         smIv= (float*)(smc + SMIV_OFF);

    const int tid  = threadIdx.x;
    const int lane = tid & 31, wrp = tid >> 5;
    const int wm   = wrp >> 1, wn = wrp & 1;    /* warp tile: 32e x 32n */
    const int gq    = blockIdx.x;               /* group of 4 trees */
    const int etile = blockIdx.y;               /* 4 tiles of 128 edges */

    /* load A tile (128 x 256) once */
    for (int i = tid; i < 128*32; i += 256) {
        int m = i >> 5, kq = i & 31;
        *(uint4*)&smA[m*APAD + kq*8] =
            *(const uint4*)&g_maskA[(size_t)(etile*128 + m)*KPAD + kq*8];
    }

    /* per-lane ldmatrix address components */
    const u32 a_row = (u32)(wm*32 + (lane & 7) + ((lane >> 3) & 1)*8);
    const u32 a_kk  = (u32)((lane >> 4)*8);
    const u32 b_row = (u32)(wn*32 + (lane & 7) + (lane >> 4)*8);
    const u32 b_kk  = (u32)(((lane >> 3) & 1)*8);
    const u32 aBase = smem + SMA_OFF;
    const u32 bBase = smem + SMB_OFF;

    for (int gi = 0; gi < 4; gi++) {
        const int g = gq*4 + gi;
        __syncthreads();            /* previous-iteration readers done */
        /* load B tile (64 x 256) + iv */
        for (int i = tid; i < 64*32; i += 256) {
            int n = i >> 5, kq = i & 31;
            *(uint4*)&smB[n*APAD + kq*8] =
                *(const uint4*)&g_poolT[(size_t)(g*64 + n)*KPAD + kq*8];
        }
        if (tid < 128)
            smIv[tid] = g_minv[(size_t)(etile*128 + tid)*NGT + g];
        __syncthreads();

        float c[2][4][4];
        #pragma unroll
        for (int mf = 0; mf < 2; mf++)
            #pragma unroll
            for (int nf = 0; nf < 4; nf++)
                #pragma unroll
                for (int q = 0; q < 4; q++) c[mf][nf][q] = 0.f;

        #pragma unroll 4
        for (int ks = 0; ks < 16; ks++) {
            u32 a[2][4], b[4][2];
            #pragma unroll
            for (int mf = 0; mf < 2; mf++) {
                u32 ad = aBase + ((a_row + mf*16)*APAD + ks*16 + a_kk)*2;
                LDSM_X4(a[mf][0], a[mf][1], a[mf][2], a[mf][3], ad);
            }
            #pragma unroll
            for (int nh = 0; nh < 2; nh++) {
                u32 bd = bBase + ((b_row + nh*16)*APAD + ks*16 + b_kk)*2;
                LDSM_X4(b[nh*2][0], b[nh*2][1], b[nh*2+1][0], b[nh*2+1][1], bd);
            }
            #pragma unroll
            for (int mf = 0; mf < 2; mf++)
                #pragma unroll
                for (int nf = 0; nf < 4; nf++)
                    MMA_BF16(c[mf][nf][0], c[mf][nf][1], c[mf][nf][2], c[mf][nf][3],
                             a[mf][0], a[mf][1], a[mf][2], a[mf][3],
                             b[nf][0], b[nf][1]);
        }

        /* epilogue: scale by minv, write g_gt[e][g*64 + d] */
        #pragma unroll
        for (int mf = 0; mf < 2; mf++) {
            int mLoc = wm*32 + mf*16 + (lane >> 2);
            int eLo = etile*128 + mLoc;
            int eHi = eLo + 8;
            float ivLo = smIv[mLoc], ivHi = smIv[mLoc + 8];
            #pragma unroll
            for (int nf = 0; nf < 4; nf++) {
                int d = wn*32 + nf*8 + (lane & 3)*2;
                if (eLo < NED) {
                    float2 v; v.x = c[mf][nf][0]*ivLo; v.y = c[mf][nf][1]*ivLo;
                    *(float2*)&g_gt[(size_t)eLo*GTS + g*64 + d] = v;
                }
                if (eHi < NED) {
                    float2 v; v.x = c[mf][nf][2]*ivHi; v.y = c[mf][nf][3]*ivHi;
                    *(float2*)&g_gt[(size_t)eHi*GTS + g*64 + d] = v;
                }
            }
        }
    }
}

/* ================= kernel 4: per-edge mean / unbiased std ================ */
__global__ void __launch_bounds__(256, 4)
stats_kernel(float* __restrict__ out)
{
    __shared__ float red[256];
    __shared__ float meanb[DD];
    const int e = blockIdx.x, tid = threadIdx.x;
    const int d = tid & 63, part = tid >> 6;
    const float nv = g_nv[e];
    const float* gt = g_gt + (size_t)e*GTS;

    float s1 = 0.f;
    for (int gg = part*128; gg < part*128 + 128; gg++) s1 += gt[gg*DD + d];
    red[tid] = s1;
    __syncthreads();
    if (tid < 64) {
        float tot = red[d] + red[64+d] + red[128+d] + red[192+d];
        float mn = tot / fmaxf(nv, 1.f);
        meanb[d] = mn;
        out[(size_t)e*2*DD + d] = mn;
    }
    __syncthreads();
    float mn = meanb[d];
    float s2 = 0.f;
    for (int gg = part*128; gg < part*128 + 128; gg++) {
        if (g_minv[(size_t)e*NGT + gg] > 0.f) {
            float dv = gt[gg*DD + d] - mn;
            s2 = fmaf(dv, dv, s2);
        }
    }
    red[tid] = s2;
    __syncthreads();
    if (tid < 64) {
        float tot = red[d] + red[64+d] + red[128+d] + red[192+d];
        float var = tot / fmaxf(nv - 1.f, 1.f);
        out[(size_t)e*2*DD + DD + d] = (nv > 1.f) ? sqrtf(var) : 0.f;
    }
}

/* ------------------------------ host -------------------------------------*/
extern "C" void kernel_launch(void* const* d_in, const int* in_sizes, int n_in,
                              void* d_out, int out_size)
{
    int o = (n_in > 5 && in_sizes[5] == (NSP+1)*DD) ? 0 : 1;

    const int* edge = (const int*)d_in[0];
    const int* sp   = (const int*)d_in[1];
    const u8*  leaf = (const u8*)d_in[2];
    const u8*  clad = (const u8*)d_in[4];
    const float* emb = (const float*)d_in[5+o];
    const float* W1  = (const float*)d_in[6+o];
    const float* b1  = (const float*)d_in[7+o];
    const float* W2  = (const float*)d_in[8+o];
    const float* b2  = (const float*)d_in[9+o];
    const float* eps = (const float*)d_in[10+o];
    const float* gam = (const float*)d_in[11+o];
    const float* bet = (const float*)d_in[12+o];

    const int smem1 = (2*RSA + 2048 + 256)*4 + (400+401+400+204+400)*4 + 400*2 + 400;
    cudaFuncSetAttribute(gin_kernel,      cudaFuncAttributeMaxDynamicSharedMemorySize, smem1);
    cudaFuncSetAttribute(gemm_mma_kernel, cudaFuncAttributeMaxDynamicSharedMemorySize, SMG_TOT);

    gin_kernel<<<NGT, 512, smem1>>>(edge, sp, leaf, emb, W1, b1, W2, b2, eps, gam, bet);
    maskprep_kernel<<<EPAD, KPAD>>>(clad, leaf);
    transpose_kernel<<<4096, 256>>>();
    cnt_kernel<<<NED, 256>>>(clad, leaf);
    gemm_mma_kernel<<<dim3(128, 4), 256, SMG_TOT>>>();
    stats_kernel<<<NED, 256>>>((float*)d_out);
    (void)out_size; (void)n_in;
}

// round 8
// speedup vs baseline: 5.7976x; 1.7406x over previous
#include <cuda_runtime.h>
#include <cuda_bf16.h>
#include <cstdint>

#define NGT 512
#define NN  399
#define NSP 200
#define NED 397
#define DD  64
#define EPT 398
#define ECOLS (NGT*EPT*2)
#define RS  65                 /* xb fp32 row stride */
#define HSF 68                 /* hstage fp32 row stride (A-frag conflict-free) */
#define WS  72                 /* W fp32 row stride (B-frag conflict-free) */
#define GTS (NGT*DD)
#define KPAD 256
#define EPAD 512

/* gin smem float offsets */
#define VEC_F  26000
#define INT_F  26256
#define WB1_F  28368
#define WB2_F  32976
#define HST_F  37584
#define GIN_SMEM ((HST_F + 16*1088)*4)   /* 219968 B */

typedef unsigned char u8;
typedef unsigned long long ull;
typedef unsigned int u32;
typedef unsigned short u16;

/* ---------------- scratch (static device globals) ----------------------- */
__device__ __nv_bfloat16 g_pool_bf[(size_t)NSP*NGT*DD];   /* [s][g][d] 13MB */
__device__ __nv_bfloat16 g_poolT[(size_t)GTS*KPAD];       /* [gd][s] 16.8MB */
__device__ __nv_bfloat16 g_maskA[(size_t)EPAD*KPAD];      /* [e][s] */
__device__ float g_valid[NSP*NGT];                        /* [s][g] */
__device__ float g_gt[(size_t)400*GTS];                   /* [e][g][d] 52MB */
__device__ float g_minv[(size_t)EPAD*NGT];                /* [e][g] */

__device__ __forceinline__ u32 smem_u32(const void* p){
    u32 a; asm("{ .reg .u64 t; cvta.to.shared.u64 t, %1; cvt.u32.u64 %0, t; }" : "=r"(a) : "l"(p));
    return a;
}
__device__ __forceinline__ u32 f2tf(float f){
    u32 r; asm("cvt.rna.tf32.f32 %0, %1;" : "=r"(r) : "f"(f)); return r;
}
#define LDSM_X4(r0,r1,r2,r3,addr) \
    asm volatile("ldmatrix.sync.aligned.m8n8.x4.shared.b16 {%0,%1,%2,%3}, [%4];" \
        : "=r"(r0), "=r"(r1), "=r"(r2), "=r"(r3) : "r"(addr))
#define MMA_BF16(c0,c1,c2,c3,a0,a1,a2,a3,b0,b1) \
    asm volatile("mma.sync.aligned.m16n8k16.row.col.f32.bf16.bf16.f32 " \
        "{%0,%1,%2,%3},{%4,%5,%6,%7},{%8,%9},{%0,%1,%2,%3};" \
        : "+f"(c0), "+f"(c1), "+f"(c2), "+f"(c3) \
        : "r"(a0), "r"(a1), "r"(a2), "r"(a3), "r"(b0), "r"(b1))
#define MMA_TF32(c0,c1,c2,c3,a0,a1,a2,a3,b0,b1) \
    asm volatile("mma.sync.aligned.m16n8k8.row.col.f32.tf32.tf32.f32 " \
        "{%0,%1,%2,%3},{%4,%5,%6,%7},{%8,%9},{%0,%1,%2,%3};" \
        : "+f"(c0), "+f"(c1), "+f"(c2), "+f"(c3) \
        : "r"(a0), "r"(a1), "r"(a2), "r"(a3), "r"(b0), "r"(b1))

/* ---------------- per-chunk GIN pipeline (one warp, 16 rows) ------------- */
__device__ __forceinline__ void gin_chunk(
    float* __restrict__ xb, const float* __restrict__ vec,
    const int* __restrict__ ipar, const int* __restrict__ ioff,
    const int* __restrict__ ilist,
    float* __restrict__ hst, const float* __restrict__ wb1,
    const float* __restrict__ wb2,
    int m0, int lane, float e1, int toSlot, float* yreg)
{
    const int lr = lane >> 2, lc = lane & 3;

    /* gather 16 rows -> hst (tf32-rounded fp32 bits) */
    for (int r = 0; r < 16; r++) {
        int row = m0 + r;
        float a0 = 0.f, a1 = 0.f;
        if (row < NN) {
            a0 = e1 * xb[row*RS + lane];
            a1 = e1 * xb[row*RS + lane + 32];
            if (row > 0) {
                int p = ipar[row];
                a0 += xb[p*RS + lane];
                a1 += xb[p*RS + lane + 32];
            }
            int oe = ioff[row+1];
            for (int j = ioff[row]; j < oe; j++) {
                int ci = ilist[j];
                a0 += xb[ci*RS + lane];
                a1 += xb[ci*RS + lane + 32];
            }
        }
        hst[r*HSF + lane]      = __uint_as_float(f2tf(a0));
        hst[r*HSF + lane + 32] = __uint_as_float(f2tf(a1));
    }
    __syncwarp();

    float acc[8][4];
    /* mm1: t = h @ W1 */
    #pragma unroll
    for (int nt = 0; nt < 8; nt++) { acc[nt][0]=0.f; acc[nt][1]=0.f; acc[nt][2]=0.f; acc[nt][3]=0.f; }
    #pragma unroll
    for (int ks = 0; ks < 8; ks++) {
        u32 a0 = __float_as_uint(hst[lr*HSF + ks*8 + lc]);
        u32 a1 = __float_as_uint(hst[(lr+8)*HSF + ks*8 + lc]);
        u32 a2 = __float_as_uint(hst[lr*HSF + ks*8 + lc + 4]);
        u32 a3 = __float_as_uint(hst[(lr+8)*HSF + ks*8 + lc + 4]);
        #pragma unroll
        for (int nt = 0; nt < 8; nt++) {
            u32 b0 = __float_as_uint(wb1[(ks*8 + lc)*WS + nt*8 + lr]);
            u32 b1 = __float_as_uint(wb1[(ks*8 + lc + 4)*WS + nt*8 + lr]);
            MMA_TF32(acc[nt][0],acc[nt][1],acc[nt][2],acc[nt][3], a0,a1,a2,a3, b0,b1);
        }
    }
    __syncwarp();
    /* relu(t + b1) -> hst */
    #pragma unroll
    for (int nt = 0; nt < 8; nt++) {
        int col = nt*8 + lc*2;
        hst[lr*HSF + col]       = __uint_as_float(f2tf(fmaxf(acc[nt][0] + vec[col],   0.f)));
        hst[lr*HSF + col + 1]   = __uint_as_float(f2tf(fmaxf(acc[nt][1] + vec[col+1], 0.f)));
        hst[(lr+8)*HSF + col]   = __uint_as_float(f2tf(fmaxf(acc[nt][2] + vec[col],   0.f)));
        hst[(lr+8)*HSF + col+1] = __uint_as_float(f2tf(fmaxf(acc[nt][3] + vec[col+1], 0.f)));
    }
    __syncwarp();
    /* mm2: y = t @ W2 */
    #pragma unroll
    for (int nt = 0; nt < 8; nt++) { acc[nt][0]=0.f; acc[nt][1]=0.f; acc[nt][2]=0.f; acc[nt][3]=0.f; }
    #pragma unroll
    for (int ks = 0; ks < 8; ks++) {
        u32 a0 = __float_as_uint(hst[lr*HSF + ks*8 + lc]);
        u32 a1 = __float_as_uint(hst[(lr+8)*HSF + ks*8 + lc]);
        u32 a2 = __float_as_uint(hst[lr*HSF + ks*8 + lc + 4]);
        u32 a3 = __float_as_uint(hst[(lr+8)*HSF + ks*8 + lc + 4]);
        #pragma unroll
        for (int nt = 0; nt < 8; nt++) {
            u32 b0 = __float_as_uint(wb2[(ks*8 + lc)*WS + nt*8 + lr]);
            u32 b1 = __float_as_uint(wb2[(ks*8 + lc + 4)*WS + nt*8 + lr]);
            MMA_TF32(acc[nt][0],acc[nt][1],acc[nt][2],acc[nt][3], a0,a1,a2,a3, b0,b1);
        }
    }
    __syncwarp();

    /* y += b2 + residual x; LayerNorm */
    int r0 = m0 + lr, r1 = r0 + 8;
    #pragma unroll
    for (int nt = 0; nt < 8; nt++) {
        int col = nt*8 + lc*2;
        acc[nt][0] += vec[64+col]   + xb[r0*RS + col];
        acc[nt][1] += vec[64+col+1] + xb[r0*RS + col+1];
        acc[nt][2] += vec[64+col]   + xb[r1*RS + col];
        acc[nt][3] += vec[64+col+1] + xb[r1*RS + col+1];
    }
    float s0 = 0.f, s1 = 0.f;
    #pragma unroll
    for (int nt = 0; nt < 8; nt++) { s0 += acc[nt][0]+acc[nt][1]; s1 += acc[nt][2]+acc[nt][3]; }
    s0 += __shfl_xor_sync(0xffffffffu, s0, 1); s0 += __shfl_xor_sync(0xffffffffu, s0, 2);
    s1 += __shfl_xor_sync(0xffffffffu, s1, 1); s1 += __shfl_xor_sync(0xffffffffu, s1, 2);
    float mu0 = s0*(1.f/DD), mu1 = s1*(1.f/DD);
    float v0 = 0.f, v1 = 0.f;
    #pragma unroll
    for (int nt = 0; nt < 8; nt++) {
        float d;
        d = acc[nt][0]-mu0; v0 = fmaf(d,d,v0);
        d = acc[nt][1]-mu0; v0 = fmaf(d,d,v0);
        d = acc[nt][2]-mu1; v1 = fmaf(d,d,v1);
        d = acc[nt][3]-mu1; v1 = fmaf(d,d,v1);
    }
    v0 += __shfl_xor_sync(0xffffffffu, v0, 1); v0 += __shfl_xor_sync(0xffffffffu, v0, 2);
    v1 += __shfl_xor_sync(0xffffffffu, v1, 1); v1 += __shfl_xor_sync(0xffffffffu, v1, 2);
    float rs0 = rsqrtf(v0*(1.f/DD) + 1e-5f);
    float rs1 = rsqrtf(v1*(1.f/DD) + 1e-5f);
    #pragma unroll
    for (int nt = 0; nt < 8; nt++) {
        int col = nt*8 + lc*2;
        float f0 = (acc[nt][0]-mu0)*rs0*vec[128+col]   + vec[192+col];
        float f1 = (acc[nt][1]-mu0)*rs0*vec[128+col+1] + vec[192+col+1];
        float f2 = (acc[nt][2]-mu1)*rs1*vec[128+col]   + vec[192+col];
        float f3 = (acc[nt][3]-mu1)*rs1*vec[128+col+1] + vec[192+col+1];
        if (toSlot) {
            hst[lr*HSF + col] = f0;     hst[lr*HSF + col+1] = f1;
            hst[(lr+8)*HSF + col] = f2; hst[(lr+8)*HSF + col+1] = f3;
        } else {
            yreg[nt*4+0] = f0; yreg[nt*4+1] = f1; yreg[nt*4+2] = f2; yreg[nt*4+3] = f3;
        }
    }
}

/* ======================= kernel 1: GIN per tree ========================== */
__global__ void __launch_bounds__(512, 1)
gin_kernel(const int* __restrict__ edge, const int* __restrict__ sp,
           const u8* __restrict__ leaf, const float* __restrict__ emb,
           const float* __restrict__ W1, const float* __restrict__ b1,
           const float* __restrict__ W2, const float* __restrict__ b2,
           const float* __restrict__ eps, const float* __restrict__ gam,
           const float* __restrict__ bet)
{
    extern __shared__ float smf[];
    float* xb   = smf;                       /* 400 x 65 fp32 */
    float* vec  = smf + VEC_F;               /* b1|b2|gamma|beta */
    int*   ipar = (int*)(smf + INT_F);       /* 400 */
    int*   ioff = ipar + 400;                /* 401 */
    int*   ilist= ioff + 401;                /* 400 */
    int*   soff = ilist + 400;               /* 204 */
    int*   slist= soff + 204;                /* 400 */
    short* ssp  = (short*)(slist + 400);     /* 400 */
    u8*    slf  = (u8*)(ssp + 400);          /* 400 */
    float* wb1f = smf + WB1_F;               /* 64 x 72 */
    float* wb2f = smf + WB2_F;               /* 64 x 72 */
    float* hstf = smf + HST_F;               /* 16 x (16 x 68) */

    const int tid = threadIdx.x;
    const int g   = blockIdx.x;
    const int lane = tid & 31, wrp = tid >> 5;
    const int em  = (edge[1] == 0) ? 2 : 1;
    const int smu = (sp[1]   == 0) ? 2 : 1;
    const int bw  = leaf[1] ? 1 : (leaf[4] ? 4 : 8);

    for (int n = tid; n < NN; n += 512) {
        size_t gi = (size_t)g*NN + n;
        int s = sp[(size_t)smu * gi];
        ssp[n] = (short)s;
        slf[n] = (s >= 0 && leaf[gi * (size_t)bw] != 0) ? 1 : 0;
    }
    for (int n = tid; n <= NN;  n += 512) ioff[n] = 0;
    for (int s = tid; s <= NSP; s += 512) soff[s] = 0;
    __syncthreads();

    for (int i = tid; i < NN*DD; i += 512) {
        int n = i >> 6, d = i & 63;
        int s = ssp[n];
        xb[n*RS + d] = emb[(s < 0 ? NSP : s)*DD + d];
    }
    for (int e = tid; e < EPT; e += 512) {
        int p = edge[(size_t)em * ((size_t)ECOLS + (size_t)g*EPT + e)] - g*NN;
        ipar[e+1] = p;
        atomicAdd(&ioff[p], 1);
    }
    if (tid == 0) ipar[0] = 0;
    for (int n = tid; n < NN; n += 512)
        if (slf[n]) atomicAdd(&soff[ssp[n]], 1);
    __syncthreads();

    /* exclusive scans */
    if (wrp == 0) {
        int carry = 0;
        for (int base = 0; base < NN; base += 32) {
            int idx = base + lane;
            int orig = (idx < NN) ? ioff[idx] : 0;
            int v = orig;
            #pragma unroll
            for (int o = 1; o < 32; o <<= 1) { int t = __shfl_up_sync(0xffffffffu, v, o); if (lane >= o) v += t; }
            if (idx < NN) ioff[idx] = carry + v - orig;
            carry += __shfl_sync(0xffffffffu, v, 31);
        }
        if (lane == 0) ioff[NN] = carry;
    } else if (wrp == 1) {
        int carry = 0;
        for (int base = 0; base < NSP; base += 32) {
            int idx = base + lane;
            int orig = (idx < NSP) ? soff[idx] : 0;
            int v = orig;
            #pragma unroll
            for (int o = 1; o < 32; o <<= 1) { int t = __shfl_up_sync(0xffffffffu, v, o); if (lane >= o) v += t; }
            if (idx < NSP) soff[idx] = carry + v - orig;
            carry += __shfl_sync(0xffffffffu, v, 31);
        }
        if (lane == 0) soff[NSP] = carry;
    }
    __syncthreads();

    /* deterministic CSR fill via rank counting */
    for (int c = 1 + tid; c < NN; c += 512) {
        int p = ipar[c], r = 0;
        for (int c2 = 1; c2 < c; c2++) r += (ipar[c2] == p);
        ilist[ioff[p] + r] = c;
    }
    for (int n = tid; n < NN; n += 512) {
        if (slf[n]) {
            int s = ssp[n], r = 0;
            for (int n2 = 0; n2 < n; n2++) r += (slf[n2] && ssp[n2] == s);
            slist[soff[s] + r] = n;
        }
    }
    __syncthreads();

    float ypark[32];
    float* hst = hstf + wrp*1088;
    const int c0 = wrp, c1 = wrp + 16;
    const int has2 = (c1 < 25);

    for (int l = 0; l < 2; l++) {
        const float* W1l = W1 + l*DD*DD;
        const float* W2l = W2 + l*DD*DD;
        if (tid < 64) {
            vec[tid]       = b1[l*DD + tid];
            vec[64 + tid]  = b2[l*DD + tid];
            vec[128 + tid] = gam[l*DD + tid];
            vec[192 + tid] = bet[l*DD + tid];
        }
        for (int i = tid; i < DD*DD; i += 512) {
            int r = i >> 6, c = i & 63;
            wb1f[r*WS + c] = __uint_as_float(f2tf(W1l[i]));
            wb2f[r*WS + c] = __uint_as_float(f2tf(W2l[i]));
        }
        const float e1 = 1.f + eps[l];
        __syncthreads();

        if (has2) {
            gin_chunk(xb, vec, ipar, ioff, ilist, hst, wb1f, wb2f, c0*16, lane, e1, 0, ypark);
            gin_chunk(xb, vec, ipar, ioff, ilist, hst, wb1f, wb2f, c1*16, lane, e1, 1, ypark);
        } else {
            gin_chunk(xb, vec, ipar, ioff, ilist, hst, wb1f, wb2f, c0*16, lane, e1, 1, ypark);
        }
        __syncthreads();   /* all gathers/reads of xb done before writes */

        if (has2) {
            int m0 = c0*16;
            int r0 = m0 + (lane>>2), r1 = r0 + 8;
            #pragma unroll
            for (int nt = 0; nt < 8; nt++) {
                int col = nt*8 + (lane&3)*2;
                xb[r0*RS+col]   = ypark[nt*4+0];
                xb[r0*RS+col+1] = ypark[nt*4+1];
                xb[r1*RS+col]   = ypark[nt*4+2];
                xb[r1*RS+col+1] = ypark[nt*4+3];
            }
        }
        int mS = (has2 ? c1 : c0)*16;
        for (int i = lane; i < 1024; i += 32) {
            int r = i >> 6, cc = i & 63;
            if (mS + r < NN) xb[(mS+r)*RS + cc] = hst[r*HSF + cc];
        }
        __syncthreads();
    }

    /* species pooling -> bf16 pool + fp32 valid */
    for (int i = tid; i < NSP*DD; i += 512) {
        int s = i >> 6, d = i & 63;
        int o0 = soff[s], o1 = soff[s+1];
        float a = 0.f;
        for (int j = o0; j < o1; j++) a += xb[slist[j]*RS + d];
        float c = (float)(o1 - o0);
        g_pool_bf[(size_t)s*NGT*DD + (size_t)g*DD + d] = __float2bfloat16(a / fmaxf(c, 1.f));
        if (d == 0) g_valid[s*NGT + g] = (c > 0.f) ? 1.f : 0.f;
    }
}

/* ====== kernel 2: per-(edge,tree) 1/ccnt  (8 edges/CTA, valid reuse) ===== */
__global__ void __launch_bounds__(256, 2)
cnt_kernel(const u8* __restrict__ clade, const u8* __restrict__ leaf)
{
    __shared__ float msk[8][NSP];
    const int tid = threadIdx.x;
    const int e0  = blockIdx.x * 8;
    const int gg  = blockIdx.y * 256 + tid;
    const int bw  = leaf[1] ? 1 : (leaf[4] ? 4 : 8);
    for (int i = tid; i < 8*NSP; i += 256) {
        int e = i / NSP, s = i % NSP;
        int ee = e0 + e;
        msk[e][s] = (ee < NED && clade[((size_t)ee*NSP + s)*(size_t)bw]) ? 1.f : 0.f;
    }
    __syncthreads();
    float c[8];
    #pragma unroll
    for (int e = 0; e < 8; e++) c[e] = 0.f;
    for (int s = 0; s < NSP; s++) {
        float v = g_valid[s*NGT + gg];
        #pragma unroll
        for (int e = 0; e < 8; e++) c[e] = fmaf(msk[e][s], v, c[e]);
    }
    #pragma unroll
    for (int e = 0; e < 8; e++) {
        int ee = e0 + e;
        if (ee < NED)
            g_minv[(size_t)ee*NGT + gg] = (c[e] > 0.f) ? (1.f/c[e]) : 0.f;
    }
}

/* =============== kernel 2b: build bf16 mask A [EPAD x KPAD] ============= */
__global__ void maskprep_kernel(const u8* __restrict__ clade, const u8* __restrict__ leaf)
{
    const int e = blockIdx.x, s = threadIdx.x;
    const int bw = leaf[1] ? 1 : (leaf[4] ? 4 : 8);
    float v = 0.f;
    if (e < NED && s < NSP && clade[((size_t)e*NSP + s)*(size_t)bw]) v = 1.f;
    g_maskA[(size_t)e*KPAD + s] = __float2bfloat16(v);
}

/* =========== kernel 2c: tiled transpose pool -> poolT [gd][s] =========== */
__global__ void __launch_bounds__(256)
transpose_kernel()
{
    __shared__ u16 t[32][40];
    const int tid = threadIdx.x;
    const int gd0 = blockIdx.x * 32;
    const int s0  = blockIdx.y * 32;
    for (int i = tid; i < 1024; i += 256) {
        int sr = i >> 5, gdc = i & 31;
        int s = s0 + sr;
        t[sr][gdc] = (s < NSP) ? *(const u16*)&g_pool_bf[(size_t)s*GTS + gd0 + gdc] : (u16)0;
    }
    __syncthreads();
    for (int i = tid; i < 1024; i += 256) {
        int gdr = i >> 5, sc = i & 31;
        *(u16*)&g_poolT[(size_t)(gd0 + gdr)*KPAD + s0 + sc] = t[sc][gdr];
    }
}

/* ====== kernel 3: mma.sync bf16 GEMM  C[e,gd] = sum_s M[e,s] P[gd,s] ==== */
#define APAD 264
#define SMA_OFF 0
#define SMB_OFF (128*APAD*2)
#define SMIV_OFF (SMB_OFF + 64*APAD*2)
#define SMG_TOT (SMIV_OFF + 128*4)

__global__ void __launch_bounds__(256, 1)
gemm_mma_kernel()
{
    extern __shared__ char smc[];
    const u32 smem = smem_u32(smc);
    __nv_bfloat16* smA = (__nv_bfloat16*)(smc + SMA_OFF);
    __nv_bfloat16* smB = (__nv_bfloat16*)(smc + SMB_OFF);
    float*         smIv= (float*)(smc + SMIV_OFF);

    const int tid  = threadIdx.x;
    const int lane = tid & 31, wrp = tid >> 5;
    const int wm   = wrp >> 1, wn = wrp & 1;
    const int gq    = blockIdx.x;
    const int etile = blockIdx.y;

    for (int i = tid; i < 128*32; i += 256) {
        int m = i >> 5, kq = i & 31;
        *(uint4*)&smA[m*APAD + kq*8] =
            *(const uint4*)&g_maskA[(size_t)(etile*128 + m)*KPAD + kq*8];
    }

    const u32 a_row = (u32)(wm*32 + (lane & 7) + ((lane >> 3) & 1)*8);
    const u32 a_kk  = (u32)((lane >> 4)*8);
    const u32 b_row = (u32)(wn*32 + (lane & 7) + (lane >> 4)*8);
    const u32 b_kk  = (u32)(((lane >> 3) & 1)*8);
    const u32 aBase = smem + SMA_OFF;
    const u32 bBase = smem + SMB_OFF;

    for (int gi = 0; gi < 4; gi++) {
        const int g = gq*4 + gi;
        __syncthreads();
        for (int i = tid; i < 64*32; i += 256) {
            int n = i >> 5, kq = i & 31;
            *(uint4*)&smB[n*APAD + kq*8] =
                *(const uint4*)&g_poolT[(size_t)(g*64 + n)*KPAD + kq*8];
        }
        if (tid < 128)
            smIv[tid] = g_minv[(size_t)(etile*128 + tid)*NGT + g];
        __syncthreads();

        float c[2][4][4];
        #pragma unroll
        for (int mf = 0; mf < 2; mf++)
            #pragma unroll
            for (int nf = 0; nf < 4; nf++)
                #pragma unroll
                for (int q = 0; q < 4; q++) c[mf][nf][q] = 0.f;

        #pragma unroll 4
        for (int ks = 0; ks < 16; ks++) {
            u32 a[2][4], b[4][2];
            #pragma unroll
            for (int mf = 0; mf < 2; mf++) {
                u32 ad = aBase + ((a_row + mf*16)*APAD + ks*16 + a_kk)*2;
                LDSM_X4(a[mf][0], a[mf][1], a[mf][2], a[mf][3], ad);
            }
            #pragma unroll
            for (int nh = 0; nh < 2; nh++) {
                u32 bd = bBase + ((b_row + nh*16)*APAD + ks*16 + b_kk)*2;
                LDSM_X4(b[nh*2][0], b[nh*2][1], b[nh*2+1][0], b[nh*2+1][1], bd);
            }
            #pragma unroll
            for (int mf = 0; mf < 2; mf++)
                #pragma unroll
                for (int nf = 0; nf < 4; nf++)
                    MMA_BF16(c[mf][nf][0], c[mf][nf][1], c[mf][nf][2], c[mf][nf][3],
                             a[mf][0], a[mf][1], a[mf][2], a[mf][3],
                             b[nf][0], b[nf][1]);
        }

        #pragma unroll
        for (int mf = 0; mf < 2; mf++) {
            int mLoc = wm*32 + mf*16 + (lane >> 2);
            int eLo = etile*128 + mLoc;
            int eHi = eLo + 8;
            float ivLo = smIv[mLoc], ivHi = smIv[mLoc + 8];
            #pragma unroll
            for (int nf = 0; nf < 4; nf++) {
                int d = wn*32 + nf*8 + (lane & 3)*2;
                if (eLo < NED) {
                    float2 v; v.x = c[mf][nf][0]*ivLo; v.y = c[mf][nf][1]*ivLo;
                    *(float2*)&g_gt[(size_t)eLo*GTS + g*64 + d] = v;
                }
                if (eHi < NED) {
                    float2 v; v.x = c[mf][nf][2]*ivHi; v.y = c[mf][nf][3]*ivHi;
                    *(float2*)&g_gt[(size_t)eHi*GTS + g*64 + d] = v;
                }
            }
        }
    }
}

/* ================= kernel 4: per-edge mean / unbiased std ================ */
__global__ void __launch_bounds__(256, 4)
stats_kernel(float* __restrict__ out)
{
    __shared__ float red[256], redc[256], meanb[DD];
    const int e = blockIdx.x, tid = threadIdx.x;
    const int d = tid & 63, part = tid >> 6;
    const float* gt = g_gt + (size_t)e*GTS;

    float s1 = 0.f, cnt = 0.f;
    for (int gg = part*128; gg < part*128 + 128; gg++) {
        s1 += gt[gg*DD + d];
        cnt += (g_minv[(size_t)e*NGT + gg] > 0.f) ? 1.f : 0.f;
    }
    red[tid] = s1; redc[tid] = cnt;
    __syncthreads();
    if (tid < 64) {
        float nv = redc[d] + redc[64+d] + redc[128+d] + redc[192+d];
        float tot = red[d] + red[64+d] + red[128+d] + red[192+d];
        float mn = tot / fmaxf(nv, 1.f);
        meanb[d] = mn;
        out[(size_t)e*2*DD + d] = mn;
    }
    __syncthreads();
    float mn = meanb[d];
    float s2 = 0.f;
    for (int gg = part*128; gg < part*128 + 128; gg++) {
        if (g_minv[(size_t)e*NGT + gg] > 0.f) {
            float dv = gt[gg*DD + d] - mn;
            s2 = fmaf(dv, dv, s2);
        }
    }
    red[tid] = s2;
    __syncthreads();
    if (tid < 64) {
        float nv = redc[d] + redc[64+d] + redc[128+d] + redc[192+d];
        float tot = red[d] + red[64+d] + red[128+d] + red[192+d];
        float var = tot / fmaxf(nv - 1.f, 1.f);
        out[(size_t)e*2*DD + DD + d] = (nv > 1.f) ? sqrtf(var) : 0.f;
    }
}

/* ------------------------------ host -------------------------------------*/
extern "C" void kernel_launch(void* const* d_in, const int* in_sizes, int n_in,
                              void* d_out, int out_size)
{
    int o = (n_in > 5 && in_sizes[5] == (NSP+1)*DD) ? 0 : 1;

    const int* edge = (const int*)d_in[0];
    const int* sp   = (const int*)d_in[1];
    const u8*  leaf = (const u8*)d_in[2];
    const u8*  clad = (const u8*)d_in[4];
    const float* emb = (const float*)d_in[5+o];
    const float* W1  = (const float*)d_in[6+o];
    const float* b1  = (const float*)d_in[7+o];
    const float* W2  = (const float*)d_in[8+o];
    const float* b2  = (const float*)d_in[9+o];
    const float* eps = (const float*)d_in[10+o];
    const float* gam = (const float*)d_in[11+o];
    const float* bet = (const float*)d_in[12+o];

    cudaFuncSetAttribute(gin_kernel,      cudaFuncAttributeMaxDynamicSharedMemorySize, GIN_SMEM);
    cudaFuncSetAttribute(gemm_mma_kernel, cudaFuncAttributeMaxDynamicSharedMemorySize, SMG_TOT);

    gin_kernel<<<NGT, 512, GIN_SMEM>>>(edge, sp, leaf, emb, W1, b1, W2, b2, eps, gam, bet);
    maskprep_kernel<<<EPAD, KPAD>>>(clad, leaf);
    transpose_kernel<<<dim3(GTS/32, KPAD/32), 256>>>();
    cnt_kernel<<<dim3(50, 2), 256>>>(clad, leaf);
    gemm_mma_kernel<<<dim3(128, 4), 256, SMG_TOT>>>();
    stats_kernel<<<NED, 256>>>((float*)d_out);
    (void)out_size; (void)n_in;
}

// round 9
// speedup vs baseline: 6.1697x; 1.0642x over previous
#include <cuda_runtime.h>
#include <cuda_bf16.h>
#include <cuda_fp16.h>
#include <cstdint>

#define NGT 512
#define NN  399
#define NSP 200
#define NED 397
#define DD  64
#define EPT 398
#define ECOLS (NGT*EPT*2)
#define RS  65
#define HS  72                 /* fp16 row stride (conflict-free ldmatrix) */
#define GTS (NGT*DD)
#define KPAD 256
#define EPAD 512

/* gin smem layout (bytes) */
#define GIN_HOFF 113456
#define GIN_WOFF 171056
#define GIN_SMEM 180272

typedef unsigned char u8;
typedef unsigned long long ull;
typedef unsigned int u32;
typedef unsigned short u16;

/* ---------------- scratch (static device globals) ----------------------- */
__device__ __nv_bfloat16 g_pool_bf[(size_t)NSP*NGT*DD];   /* [s][g][d] 13MB */
__device__ __nv_bfloat16 g_poolT[(size_t)GTS*KPAD];       /* [gd][s] 16.8MB */
__device__ __nv_bfloat16 g_maskA[(size_t)EPAD*KPAD];      /* [e][s] */
__device__ float g_valid[NSP*NGT];                        /* [s][g] */
__device__ float g_gt[(size_t)400*GTS];                   /* [e][g][d] 52MB */
__device__ float g_minv[(size_t)EPAD*NGT];                /* [e][g] */

__device__ __forceinline__ u32 smem_u32(const void* p){
    u32 a; asm("{ .reg .u64 t; cvta.to.shared.u64 t, %1; cvt.u32.u64 %0, t; }" : "=r"(a) : "l"(p));
    return a;
}
#define LDSM_X4(r0,r1,r2,r3,addr) \
    asm volatile("ldmatrix.sync.aligned.m8n8.x4.shared.b16 {%0,%1,%2,%3}, [%4];" \
        : "=r"(r0), "=r"(r1), "=r"(r2), "=r"(r3) : "r"(addr))
#define LDSM_X4_T(r0,r1,r2,r3,addr) \
    asm volatile("ldmatrix.sync.aligned.m8n8.x4.trans.shared.b16 {%0,%1,%2,%3}, [%4];" \
        : "=r"(r0), "=r"(r1), "=r"(r2), "=r"(r3) : "r"(addr))
#define MMA_BF16(c0,c1,c2,c3,a0,a1,a2,a3,b0,b1) \
    asm volatile("mma.sync.aligned.m16n8k16.row.col.f32.bf16.bf16.f32 " \
        "{%0,%1,%2,%3},{%4,%5,%6,%7},{%8,%9},{%0,%1,%2,%3};" \
        : "+f"(c0), "+f"(c1), "+f"(c2), "+f"(c3) \
        : "r"(a0), "r"(a1), "r"(a2), "r"(a3), "r"(b0), "r"(b1))
#define MMA_F16(c0,c1,c2,c3,a0,a1,a2,a3,b0,b1) \
    asm volatile("mma.sync.aligned.m16n8k16.row.col.f32.f16.f16.f32 " \
        "{%0,%1,%2,%3},{%4,%5,%6,%7},{%8,%9},{%0,%1,%2,%3};" \
        : "+f"(c0), "+f"(c1), "+f"(c2), "+f"(c3) \
        : "r"(a0), "r"(a1), "r"(a2), "r"(a3), "r"(b0), "r"(b1))

/* ======================= kernel 1: GIN per tree ========================== */
__global__ void __launch_bounds__(512, 1)
gin_kernel(const int* __restrict__ edge, const int* __restrict__ sp,
           const u8* __restrict__ leaf, const float* __restrict__ emb,
           const float* __restrict__ W1, const float* __restrict__ b1,
           const float* __restrict__ W2, const float* __restrict__ b2,
           const float* __restrict__ eps, const float* __restrict__ gam,
           const float* __restrict__ bet)
{
    extern __shared__ float smf[];
    float* xb   = smf;                       /* 400 x 65 fp32 */
    float* vec  = smf + 26000;               /* b1|b2|gamma|beta */
    int*   ipar = (int*)(smf + 26256);       /* 400 */
    int*   ioff = ipar + 400;                /* 401 */
    int*   ilist= ioff + 401;                /* 400 */
    int*   soff = ilist + 400;               /* 204 */
    int*   slist= soff + 204;                /* 400 */
    short* ssp  = (short*)(slist + 400);     /* 400 */
    u8*    slf  = (u8*)(ssp + 400);          /* 400 */
    __half* hbf = (__half*)((char*)smf + GIN_HOFF);  /* 400 x HS */
    __half* wbf = (__half*)((char*)smf + GIN_WOFF);  /* 64 x HS  */

    const int tid = threadIdx.x;
    const int g   = blockIdx.x;
    const int lane = tid & 31, wrp = tid >> 5;
    const int em  = (edge[1] == 0) ? 2 : 1;
    const int smu = (sp[1]   == 0) ? 2 : 1;
    const int bw  = leaf[1] ? 1 : (leaf[4] ? 4 : 8);

    for (int n = tid; n < NN; n += 512) {
        size_t gi = (size_t)g*NN + n;
        int s = sp[(size_t)smu * gi];
        ssp[n] = (short)s;
        slf[n] = (s >= 0 && leaf[gi * (size_t)bw] != 0) ? 1 : 0;
    }
    for (int n = tid; n <= NN;  n += 512) ioff[n] = 0;
    for (int s = tid; s <= NSP; s += 512) soff[s] = 0;
    __syncthreads();

    for (int i = tid; i < NN*DD; i += 512) {
        int n = i >> 6, d = i & 63;
        int s = ssp[n];
        xb[n*RS + d] = emb[(s < 0 ? NSP : s)*DD + d];
    }
    for (int e = tid; e < EPT; e += 512) {
        int p = edge[(size_t)em * ((size_t)ECOLS + (size_t)g*EPT + e)] - g*NN;
        ipar[e+1] = p;
        atomicAdd(&ioff[p], 1);
    }
    if (tid == 0) ipar[0] = 0;
    for (int n = tid; n < NN; n += 512)
        if (slf[n]) atomicAdd(&soff[ssp[n]], 1);
    __syncthreads();

    /* exclusive scans */
    if (wrp == 0) {
        int carry = 0;
        for (int base = 0; base < NN; base += 32) {
            int idx = base + lane;
            int orig = (idx < NN) ? ioff[idx] : 0;
            int v = orig;
            #pragma unroll
            for (int o = 1; o < 32; o <<= 1) { int t = __shfl_up_sync(0xffffffffu, v, o); if (lane >= o) v += t; }
            if (idx < NN) ioff[idx] = carry + v - orig;
            carry += __shfl_sync(0xffffffffu, v, 31);
        }
        if (lane == 0) ioff[NN] = carry;
    } else if (wrp == 1) {
        int carry = 0;
        for (int base = 0; base < NSP; base += 32) {
            int idx = base + lane;
            int orig = (idx < NSP) ? soff[idx] : 0;
            int v = orig;
            #pragma unroll
            for (int o = 1; o < 32; o <<= 1) { int t = __shfl_up_sync(0xffffffffu, v, o); if (lane >= o) v += t; }
            if (idx < NSP) soff[idx] = carry + v - orig;
            carry += __shfl_sync(0xffffffffu, v, 31);
        }
        if (lane == 0) soff[NSP] = carry;
    }
    __syncthreads();

    /* deterministic CSR fill via rank counting */
    for (int c = 1 + tid; c < NN; c += 512) {
        int p = ipar[c], r = 0;
        for (int c2 = 1; c2 < c; c2++) r += (ipar[c2] == p);
        ilist[ioff[p] + r] = c;
    }
    for (int n = tid; n < NN; n += 512) {
        if (slf[n]) {
            int s = ssp[n], r = 0;
            for (int n2 = 0; n2 < n; n2++) r += (slf[n2] && ssp[n2] == s);
            slist[soff[s] + r] = n;
        }
    }
    __syncthreads();

    /* ldmatrix per-lane address components */
    const u32 hbf_u = smem_u32(hbf);
    const u32 wbf_u = smem_u32(wbf);
    const u32 a_row = (u32)((lane & 7) + ((lane >> 3) & 1)*8);
    const u32 a_kk  = (u32)((lane >> 4)*8);
    const u32 w_row = (u32)((lane & 7) + ((lane >> 3) & 1)*8);  /* k within 16 */
    const u32 w_col = (u32)((lane >> 4)*8);                      /* n within 16 */

    for (int l = 0; l < 2; l++) {
        const float* W1l = W1 + l*DD*DD;
        const float* W2l = W2 + l*DD*DD;
        if (tid < 64) {
            vec[tid]       = b1[l*DD + tid];
            vec[64 + tid]  = b2[l*DD + tid];
            vec[128 + tid] = gam[l*DD + tid];
            vec[192 + tid] = bet[l*DD + tid];
        }
        /* stage W1 fp16 */
        for (int i = tid; i < DD*DD; i += 512)
            wbf[(i >> 6)*HS + (i & 63)] = __float2half_rn(W1l[i]);
        const float e1 = 1.f + eps[l];
        __syncthreads();

        /* gather -> h (fp32 math, fp16 store) */
        for (int i = tid; i < NN*DD; i += 512) {
            int n = i >> 6, d = i & 63;
            float a = e1 * xb[n*RS + d];
            if (n > 0) a += xb[ipar[n]*RS + d];
            int o1 = ioff[n+1];
            for (int j = ioff[n]; j < o1; j++) a += xb[ilist[j]*RS + d];
            hbf[n*HS + d] = __float2half_rn(a);
        }
        __syncthreads();

        /* matmul1: t = relu(h @ W1 + b1) -> hbf (in place) */
        for (int c0 = wrp; c0 < 25; c0 += 16) {
            int m0 = c0*16;
            float acc[8][4];
            #pragma unroll
            for (int nt = 0; nt < 8; nt++)
                #pragma unroll
                for (int q = 0; q < 4; q++) acc[nt][q] = 0.f;
            #pragma unroll
            for (int ks = 0; ks < 4; ks++) {
                u32 a0,a1,a2,a3;
                LDSM_X4(a0,a1,a2,a3, hbf_u + (((u32)m0 + a_row)*HS + (u32)ks*16 + a_kk)*2);
                u32 b[8][2];
                #pragma unroll
                for (int np = 0; np < 4; np++)
                    LDSM_X4_T(b[np*2][0], b[np*2][1], b[np*2+1][0], b[np*2+1][1],
                              wbf_u + (((u32)ks*16 + w_row)*HS + (u32)np*16 + w_col)*2);
                #pragma unroll
                for (int nt = 0; nt < 8; nt++)
                    MMA_F16(acc[nt][0],acc[nt][1],acc[nt][2],acc[nt][3],
                            a0,a1,a2,a3, b[nt][0],b[nt][1]);
            }
            int r0 = m0 + (lane >> 2), r1 = r0 + 8;
            #pragma unroll
            for (int nt = 0; nt < 8; nt++) {
                int col = nt*8 + (lane & 3)*2;
                float bb0 = vec[col], bb1 = vec[col+1];
                *(__half2*)&hbf[r0*HS + col] = __floats2half2_rn(
                    fmaxf(acc[nt][0] + bb0, 0.f), fmaxf(acc[nt][1] + bb1, 0.f));
                *(__half2*)&hbf[r1*HS + col] = __floats2half2_rn(
                    fmaxf(acc[nt][2] + bb0, 0.f), fmaxf(acc[nt][3] + bb1, 0.f));
            }
        }
        __syncthreads();

        /* stage W2 fp16 */
        for (int i = tid; i < DD*DD; i += 512)
            wbf[(i >> 6)*HS + (i & 63)] = __float2half_rn(W2l[i]);
        __syncthreads();

        /* matmul2 + residual + LayerNorm -> xb */
        for (int c0 = wrp; c0 < 25; c0 += 16) {
            int m0 = c0*16;
            float acc[8][4];
            #pragma unroll
            for (int nt = 0; nt < 8; nt++)
                #pragma unroll
                for (int q = 0; q < 4; q++) acc[nt][q] = 0.f;
            #pragma unroll
            for (int ks = 0; ks < 4; ks++) {
                u32 a0,a1,a2,a3;
                LDSM_X4(a0,a1,a2,a3, hbf_u + (((u32)m0 + a_row)*HS + (u32)ks*16 + a_kk)*2);
                u32 b[8][2];
                #pragma unroll
                for (int np = 0; np < 4; np++)
                    LDSM_X4_T(b[np*2][0], b[np*2][1], b[np*2+1][0], b[np*2+1][1],
                              wbf_u + (((u32)ks*16 + w_row)*HS + (u32)np*16 + w_col)*2);
                #pragma unroll
                for (int nt = 0; nt < 8; nt++)
                    MMA_F16(acc[nt][0],acc[nt][1],acc[nt][2],acc[nt][3],
                            a0,a1,a2,a3, b[nt][0],b[nt][1]);
            }
            int r0 = m0 + (lane >> 2), r1 = r0 + 8;
            float y0[16], y1[16];
            #pragma unroll
            for (int nt = 0; nt < 8; nt++) {
                int col = nt*8 + (lane & 3)*2;
                float b20 = vec[64+col], b21 = vec[64+col+1];
                y0[2*nt]   = acc[nt][0] + b20 + xb[r0*RS + col];
                y0[2*nt+1] = acc[nt][1] + b21 + xb[r0*RS + col+1];
                y1[2*nt]   = acc[nt][2] + b20 + xb[r1*RS + col];
                y1[2*nt+1] = acc[nt][3] + b21 + xb[r1*RS + col+1];
            }
            float s0 = 0.f, s1 = 0.f;
            #pragma unroll
            for (int q = 0; q < 16; q++) { s0 += y0[q]; s1 += y1[q]; }
            s0 += __shfl_xor_sync(0xffffffffu, s0, 1);
            s0 += __shfl_xor_sync(0xffffffffu, s0, 2);
            s1 += __shfl_xor_sync(0xffffffffu, s1, 1);
            s1 += __shfl_xor_sync(0xffffffffu, s1, 2);
            float mu0 = s0*(1.f/DD), mu1 = s1*(1.f/DD);
            float v0 = 0.f, v1 = 0.f;
            #pragma unroll
            for (int q = 0; q < 16; q++) {
                float d0 = y0[q]-mu0, d1 = y1[q]-mu1;
                v0 = fmaf(d0,d0,v0); v1 = fmaf(d1,d1,v1);
            }
            v0 += __shfl_xor_sync(0xffffffffu, v0, 1);
            v0 += __shfl_xor_sync(0xffffffffu, v0, 2);
            v1 += __shfl_xor_sync(0xffffffffu, v1, 1);
            v1 += __shfl_xor_sync(0xffffffffu, v1, 2);
            float rs0 = rsqrtf(v0*(1.f/DD) + 1e-5f);
            float rs1 = rsqrtf(v1*(1.f/DD) + 1e-5f);
            #pragma unroll
            for (int nt = 0; nt < 8; nt++) {
                int col = nt*8 + (lane & 3)*2;
                xb[r0*RS + col]   = (y0[2*nt]  -mu0)*rs0*vec[128+col]   + vec[192+col];
                xb[r0*RS + col+1] = (y0[2*nt+1]-mu0)*rs0*vec[128+col+1] + vec[192+col+1];
                xb[r1*RS + col]   = (y1[2*nt]  -mu1)*rs1*vec[128+col]   + vec[192+col];
                xb[r1*RS + col+1] = (y1[2*nt+1]-mu1)*rs1*vec[128+col+1] + vec[192+col+1];
            }
        }
        __syncthreads();
    }

    /* species pooling -> bf16 pool + fp32 valid */
    for (int i = tid; i < NSP*DD; i += 512) {
        int s = i >> 6, d = i & 63;
        int o0 = soff[s], o1 = soff[s+1];
        float a = 0.f;
        for (int j = o0; j < o1; j++) a += xb[slist[j]*RS + d];
        float c = (float)(o1 - o0);
        g_pool_bf[(size_t)s*NGT*DD + (size_t)g*DD + d] = __float2bfloat16(a / fmaxf(c, 1.f));
        if (d == 0) g_valid[s*NGT + g] = (c > 0.f) ? 1.f : 0.f;
    }
}

/* ====== kernel 2: per-(edge,tree) 1/ccnt (8 edges/CTA, MLP-8 loads) ===== */
__global__ void __launch_bounds__(256, 2)
cnt_kernel(const u8* __restrict__ clade, const u8* __restrict__ leaf)
{
    __shared__ float msk[8][NSP];
    const int tid = threadIdx.x;
    const int e0  = blockIdx.x * 8;
    const int gg  = blockIdx.y * 256 + tid;
    const int bw  = leaf[1] ? 1 : (leaf[4] ? 4 : 8);
    for (int i = tid; i < 8*NSP; i += 256) {
        int e = i / NSP, s = i % NSP;
        int ee = e0 + e;
        msk[e][s] = (ee < NED && clade[((size_t)ee*NSP + s)*(size_t)bw]) ? 1.f : 0.f;
    }
    __syncthreads();
    float c[8];
    #pragma unroll
    for (int e = 0; e < 8; e++) c[e] = 0.f;
    for (int s0 = 0; s0 < NSP; s0 += 8) {        /* NSP = 200 = 25*8 */
        float v[8];
        #pragma unroll
        for (int q = 0; q < 8; q++) v[q] = g_valid[(s0+q)*NGT + gg];
        #pragma unroll
        for (int q = 0; q < 8; q++)
            #pragma unroll
            for (int e = 0; e < 8; e++) c[e] = fmaf(msk[e][s0+q], v[q], c[e]);
    }
    #pragma unroll
    for (int e = 0; e < 8; e++) {
        int ee = e0 + e;
        if (ee < NED)
            g_minv[(size_t)ee*NGT + gg] = (c[e] > 0.f) ? (1.f/c[e]) : 0.f;
    }
}

/* =============== kernel 2b: build bf16 mask A [EPAD x KPAD] ============= */
__global__ void maskprep_kernel(const u8* __restrict__ clade, const u8* __restrict__ leaf)
{
    const int e = blockIdx.x, s = threadIdx.x;
    const int bw = leaf[1] ? 1 : (leaf[4] ? 4 : 8);
    float v = 0.f;
    if (e < NED && s < NSP && clade[((size_t)e*NSP + s)*(size_t)bw]) v = 1.f;
    g_maskA[(size_t)e*KPAD + s] = __float2bfloat16(v);
}

/* =========== kernel 2c: tiled transpose pool -> poolT [gd][s] =========== */
__global__ void __launch_bounds__(256)
transpose_kernel()
{
    __shared__ u16 t[32][40];
    const int tid = threadIdx.x;
    const int gd0 = blockIdx.x * 32;
    const int s0  = blockIdx.y * 32;
    for (int i = tid; i < 1024; i += 256) {
        int sr = i >> 5, gdc = i & 31;
        int s = s0 + sr;
        t[sr][gdc] = (s < NSP) ? *(const u16*)&g_pool_bf[(size_t)s*GTS + gd0 + gdc] : (u16)0;
    }
    __syncthreads();
    for (int i = tid; i < 1024; i += 256) {
        int gdr = i >> 5, sc = i & 31;
        *(u16*)&g_poolT[(size_t)(gd0 + gdr)*KPAD + s0 + sc] = t[sc][gdr];
    }
}

/* ====== kernel 3: mma.sync bf16 GEMM  C[e,gd] = sum_s M[e,s] P[gd,s] ==== */
#define APAD 264
#define SMA_OFF 0
#define SMB_OFF (128*APAD*2)
#define SMIV_OFF (SMB_OFF + 64*APAD*2)
#define SMG_TOT (SMIV_OFF + 128*4)

__global__ void __launch_bounds__(256, 1)
gemm_mma_kernel()
{
    extern __shared__ char smc[];
    const u32 smem = smem_u32(smc);
    __nv_bfloat16* smA = (__nv_bfloat16*)(smc + SMA_OFF);
    __nv_bfloat16* smB = (__nv_bfloat16*)(smc + SMB_OFF);
    float*         smIv= (float*)(smc + SMIV_OFF);

    const int tid  = threadIdx.x;
    const int lane = tid & 31, wrp = tid >> 5;
    const int wm   = wrp >> 1, wn = wrp & 1;
    const int gq    = blockIdx.x;
    const int etile = blockIdx.y;

    for (int i = tid; i < 128*32; i += 256) {
        int m = i >> 5, kq = i & 31;
        *(uint4*)&smA[m*APAD + kq*8] =
            *(const uint4*)&g_maskA[(size_t)(etile*128 + m)*KPAD + kq*8];
    }

    const u32 a_row = (u32)(wm*32 + (lane & 7) + ((lane >> 3) & 1)*8);
    const u32 a_kk  = (u32)((lane >> 4)*8);
    const u32 b_row = (u32)(wn*32 + (lane & 7) + (lane >> 4)*8);
    const u32 b_kk  = (u32)(((lane >> 3) & 1)*8);
    const u32 aBase = smem + SMA_OFF;
    const u32 bBase = smem + SMB_OFF;

    for (int gi = 0; gi < 4; gi++) {
        const int g = gq*4 + gi;
        __syncthreads();
        for (int i = tid; i < 64*32; i += 256) {
            int n = i >> 5, kq = i & 31;
            *(uint4*)&smB[n*APAD + kq*8] =
                *(const uint4*)&g_poolT[(size_t)(g*64 + n)*KPAD + kq*8];
        }
        if (tid < 128)
            smIv[tid] = g_minv[(size_t)(etile*128 + tid)*NGT + g];
        __syncthreads();

        float c[2][4][4];
        #pragma unroll
        for (int mf = 0; mf < 2; mf++)
            #pragma unroll
            for (int nf = 0; nf < 4; nf++)
                #pragma unroll
                for (int q = 0; q < 4; q++) c[mf][nf][q] = 0.f;

        #pragma unroll 4
        for (int ks = 0; ks < 16; ks++) {
            u32 a[2][4], b[4][2];
            #pragma unroll
            for (int mf = 0; mf < 2; mf++) {
                u32 ad = aBase + ((a_row + mf*16)*APAD + ks*16 + a_kk)*2;
                LDSM_X4(a[mf][0], a[mf][1], a[mf][2], a[mf][3], ad);
            }
            #pragma unroll
            for (int nh = 0; nh < 2; nh++) {
                u32 bd = bBase + ((b_row + nh*16)*APAD + ks*16 + b_kk)*2;
                LDSM_X4(b[nh*2][0], b[nh*2][1], b[nh*2+1][0], b[nh*2+1][1], bd);
            }
            #pragma unroll
            for (int mf = 0; mf < 2; mf++)
                #pragma unroll
                for (int nf = 0; nf < 4; nf++)
                    MMA_BF16(c[mf][nf][0], c[mf][nf][1], c[mf][nf][2], c[mf][nf][3],
                             a[mf][0], a[mf][1], a[mf][2], a[mf][3],
                             b[nf][0], b[nf][1]);
        }

        #pragma unroll
        for (int mf = 0; mf < 2; mf++) {
            int mLoc = wm*32 + mf*16 + (lane >> 2);
            int eLo = etile*128 + mLoc;
            int eHi = eLo + 8;
            float ivLo = smIv[mLoc], ivHi = smIv[mLoc + 8];
            #pragma unroll
            for (int nf = 0; nf < 4; nf++) {
                int d = wn*32 + nf*8 + (lane & 3)*2;
                if (eLo < NED) {
                    float2 v; v.x = c[mf][nf][0]*ivLo; v.y = c[mf][nf][1]*ivLo;
                    *(float2*)&g_gt[(size_t)eLo*GTS + g*64 + d] = v;
                }
                if (eHi < NED) {
                    float2 v; v.x = c[mf][nf][2]*ivHi; v.y = c[mf][nf][3]*ivHi;
                    *(float2*)&g_gt[(size_t)eHi*GTS + g*64 + d] = v;
                }
            }
        }
    }
}

/* ========= kernel 4: per-edge mean / unbiased std (single pass) ========= */
__global__ void __launch_bounds__(256, 4)
stats_kernel(float* __restrict__ out)
{
    __shared__ float red1[256], red2[256], redc[256];
    const int e = blockIdx.x, tid = threadIdx.x;
    const int d = tid & 63, part = tid >> 6;
    const float* gt = g_gt + (size_t)e*GTS;

    float s1 = 0.f, s2 = 0.f, cnt = 0.f;
    for (int gg = part*128; gg < part*128 + 128; gg++) {
        float x = gt[gg*DD + d];                 /* 0 for invalid g */
        s1 += x;
        s2 = fmaf(x, x, s2);
        cnt += (g_minv[(size_t)e*NGT + gg] > 0.f) ? 1.f : 0.f;
    }
    red1[tid] = s1; red2[tid] = s2; redc[tid] = cnt;
    __syncthreads();
    if (tid < 64) {
        float nv = redc[d] + redc[64+d] + redc[128+d] + redc[192+d];
        float t1 = red1[d] + red1[64+d] + red1[128+d] + red1[192+d];
        float t2 = red2[d] + red2[64+d] + red2[128+d] + red2[192+d];
        float mn = t1 / fmaxf(nv, 1.f);
        float var = (t2 - nv*mn*mn) / fmaxf(nv - 1.f, 1.f);
        var = fmaxf(var, 0.f);
        out[(size_t)e*2*DD + d]      = mn;
        out[(size_t)e*2*DD + DD + d] = (nv > 1.f) ? sqrtf(var) : 0.f;
    }
}

/* ------------------------------ host -------------------------------------*/
extern "C" void kernel_launch(void* const* d_in, const int* in_sizes, int n_in,
                              void* d_out, int out_size)
{
    int o = (n_in > 5 && in_sizes[5] == (NSP+1)*DD) ? 0 : 1;

    const int* edge = (const int*)d_in[0];
    const int* sp   = (const int*)d_in[1];
    const u8*  leaf = (const u8*)d_in[2];
    const u8*  clad = (const u8*)d_in[4];
    const float* emb = (const float*)d_in[5+o];
    const float* W1  = (const float*)d_in[6+o];
    const float* b1  = (const float*)d_in[7+o];
    const float* W2  = (const float*)d_in[8+o];
    const float* b2  = (const float*)d_in[9+o];
    const float* eps = (const float*)d_in[10+o];
    const float* gam = (const float*)d_in[11+o];
    const float* bet = (const float*)d_in[12+o];

    cudaFuncSetAttribute(gin_kernel,      cudaFuncAttributeMaxDynamicSharedMemorySize, GIN_SMEM);
    cudaFuncSetAttribute(gemm_mma_kernel, cudaFuncAttributeMaxDynamicSharedMemorySize, SMG_TOT);

    gin_kernel<<<NGT, 512, GIN_SMEM>>>(edge, sp, leaf, emb, W1, b1, W2, b2, eps, gam, bet);
    maskprep_kernel<<<EPAD, KPAD>>>(clad, leaf);
    transpose_kernel<<<dim3(GTS/32, KPAD/32), 256>>>();
    cnt_kernel<<<dim3(50, 2), 256>>>(clad, leaf);
    gemm_mma_kernel<<<dim3(128, 4), 256, SMG_TOT>>>();
    stats_kernel<<<NED, 256>>>((float*)d_out);
    (void)out_size; (void)n_in;
}

// round 12
// speedup vs baseline: 6.2522x; 1.0134x over previous
#include <cuda_runtime.h>
#include <cuda_bf16.h>
#include <cuda_fp16.h>
#include <cstdint>

#define NGT 512
#define NN  399
#define NSP 200
#define NED 397
#define DD  64
#define EPT 398
#define ECOLS (NGT*EPT*2)
#define RS  65
#define HS  72                 /* fp16 row stride (conflict-free ldmatrix) */
#define GTS (NGT*DD)
#define KPAD 256
#define EPAD 512

/* gin smem layout (bytes) */
#define GIN_HOFF 113456
#define GIN_WOFF 171056
#define GIN_SMEM 180272

typedef unsigned char u8;
typedef unsigned long long ull;
typedef unsigned int u32;
typedef unsigned short u16;

/* ---------------- scratch (static device globals) ----------------------- */
__device__ __nv_bfloat16 g_pool_bf[(size_t)NSP*NGT*DD];   /* [s][g][d] 13MB */
__device__ __nv_bfloat16 g_poolT[(size_t)GTS*KPAD];       /* [gd][s] 16.8MB */
__device__ __nv_bfloat16 g_maskA[(size_t)EPAD*KPAD];      /* [e][s] */
__device__ float g_valid[NSP*NGT];                        /* [s][g] */
__device__ float g_gt[(size_t)400*GTS];                   /* [e][g][d] 52MB */
__device__ float g_minv[(size_t)EPAD*NGT];                /* [e][g] */

__device__ __forceinline__ u32 smem_u32(const void* p){
    u32 a; asm("{ .reg .u64 t; cvta.to.shared.u64 t, %1; cvt.u32.u64 %0, t; }" : "=r"(a) : "l"(p));
    return a;
}
#define LDSM_X4(r0,r1,r2,r3,addr) \
    asm volatile("ldmatrix.sync.aligned.m8n8.x4.shared.b16 {%0,%1,%2,%3}, [%4];" \
        : "=r"(r0), "=r"(r1), "=r"(r2), "=r"(r3) : "r"(addr))
#define LDSM_X4_T(r0,r1,r2,r3,addr) \
    asm volatile("ldmatrix.sync.aligned.m8n8.x4.trans.shared.b16 {%0,%1,%2,%3}, [%4];" \
        : "=r"(r0), "=r"(r1), "=r"(r2), "=r"(r3) : "r"(addr))
#define MMA_BF16(c0,c1,c2,c3,a0,a1,a2,a3,b0,b1) \
    asm volatile("mma.sync.aligned.m16n8k16.row.col.f32.bf16.bf16.f32 " \
        "{%0,%1,%2,%3},{%4,%5,%6,%7},{%8,%9},{%0,%1,%2,%3};" \
        : "+f"(c0), "+f"(c1), "+f"(c2), "+f"(c3) \
        : "r"(a0), "r"(a1), "r"(a2), "r"(a3), "r"(b0), "r"(b1))
#define MMA_F16(c0,c1,c2,c3,a0,a1,a2,a3,b0,b1) \
    asm volatile("mma.sync.aligned.m16n8k16.row.col.f32.f16.f16.f32 " \
        "{%0,%1,%2,%3},{%4,%5,%6,%7},{%8,%9},{%0,%1,%2,%3};" \
        : "+f"(c0), "+f"(c1), "+f"(c2), "+f"(c3) \
        : "r"(a0), "r"(a1), "r"(a2), "r"(a3), "r"(b0), "r"(b1))

/* ======================= kernel 1: GIN per tree ========================== */
__global__ void __launch_bounds__(512, 1)
gin_kernel(const int* __restrict__ edge, const int* __restrict__ sp,
           const u8* __restrict__ leaf, const float* __restrict__ emb,
           const float* __restrict__ W1, const float* __restrict__ b1,
           const float* __restrict__ W2, const float* __restrict__ b2,
           const float* __restrict__ eps, const float* __restrict__ gam,
           const float* __restrict__ bet)
{
    extern __shared__ float smf[];
    float* xb   = smf;                       /* 400 x 65 fp32 */
    float* vec  = smf + 26000;               /* b1|b2|gamma|beta */
    int*   ipar = (int*)(smf + 26256);       /* 400 */
    int*   ioff = ipar + 400;                /* 401 */
    int*   ilist= ioff + 401;                /* 400 */
    int*   soff = ilist + 400;               /* 204 */
    int*   slist= soff + 204;                /* 400 */
    short* ssp  = (short*)(slist + 400);     /* 400 */
    u8*    slf  = (u8*)(ssp + 400);          /* 400 */
    __half* hbf = (__half*)((char*)smf + GIN_HOFF);  /* 400 x HS */
    __half* wbf = (__half*)((char*)smf + GIN_WOFF);  /* 64 x HS  */

    const int tid = threadIdx.x;
    const int g   = blockIdx.x;
    const int lane = tid & 31, wrp = tid >> 5;
    const int em  = (edge[1] == 0) ? 2 : 1;
    const int smu = (sp[1]   == 0) ? 2 : 1;
    const int bw  = leaf[1] ? 1 : (leaf[4] ? 4 : 8);

    for (int n = tid; n < NN; n += 512) {
        size_t gi = (size_t)g*NN + n;
        int s = sp[(size_t)smu * gi];
        ssp[n] = (short)s;
        slf[n] = (s >= 0 && leaf[gi * (size_t)bw] != 0) ? 1 : 0;
    }
    for (int n = tid; n <= NN;  n += 512) ioff[n] = 0;
    for (int s = tid; s <= NSP; s += 512) soff[s] = 0;
    __syncthreads();

    for (int i = tid; i < NN*DD; i += 512) {
        int n = i >> 6, d = i & 63;
        int s = ssp[n];
        xb[n*RS + d] = emb[(s < 0 ? NSP : s)*DD + d];
    }
    for (int e = tid; e < EPT; e += 512) {
        int p = edge[(size_t)em * ((size_t)ECOLS + (size_t)g*EPT + e)] - g*NN;
        ipar[e+1] = p;
        atomicAdd(&ioff[p], 1);
    }
    if (tid == 0) ipar[0] = 0;
    for (int n = tid; n < NN; n += 512)
        if (slf[n]) atomicAdd(&soff[ssp[n]], 1);
    __syncthreads();

    /* exclusive scans */
    if (wrp == 0) {
        int carry = 0;
        for (int base = 0; base < NN; base += 32) {
            int idx = base + lane;
            int orig = (idx < NN) ? ioff[idx] : 0;
            int v = orig;
            #pragma unroll
            for (int o = 1; o < 32; o <<= 1) { int t = __shfl_up_sync(0xffffffffu, v, o); if (lane >= o) v += t; }
            if (idx < NN) ioff[idx] = carry + v - orig;
            carry += __shfl_sync(0xffffffffu, v, 31);
        }
        if (lane == 0) ioff[NN] = carry;
    } else if (wrp == 1) {
        int carry = 0;
        for (int base = 0; base < NSP; base += 32) {
            int idx = base + lane;
            int orig = (idx < NSP) ? soff[idx] : 0;
            int v = orig;
            #pragma unroll
            for (int o = 1; o < 32; o <<= 1) { int t = __shfl_up_sync(0xffffffffu, v, o); if (lane >= o) v += t; }
            if (idx < NSP) soff[idx] = carry + v - orig;
            carry += __shfl_sync(0xffffffffu, v, 31);
        }
        if (lane == 0) soff[NSP] = carry;
    }
    __syncthreads();

    /* deterministic CSR fill via rank counting */
    for (int c = 1 + tid; c < NN; c += 512) {
        int p = ipar[c], r = 0;
        for (int c2 = 1; c2 < c; c2++) r += (ipar[c2] == p);
        ilist[ioff[p] + r] = c;
    }
    for (int n = tid; n < NN; n += 512) {
        if (slf[n]) {
            int s = ssp[n], r = 0;
            for (int n2 = 0; n2 < n; n2++) r += (slf[n2] && ssp[n2] == s);
            slist[soff[s] + r] = n;
        }
    }
    __syncthreads();

    /* ldmatrix per-lane address components */
    const u32 hbf_u = smem_u32(hbf);
    const u32 wbf_u = smem_u32(wbf);
    const u32 a_row = (u32)((lane & 7) + ((lane >> 3) & 1)*8);
    const u32 a_kk  = (u32)((lane >> 4)*8);
    const u32 w_row = (u32)((lane & 7) + ((lane >> 3) & 1)*8);  /* k within 16 */
    const u32 w_col = (u32)((lane >> 4)*8);                      /* n within 16 */

    for (int l = 0; l < 2; l++) {
        const float* W1l = W1 + l*DD*DD;
        const float* W2l = W2 + l*DD*DD;
        if (tid < 64) {
            vec[tid]       = b1[l*DD + tid];
            vec[64 + tid]  = b2[l*DD + tid];
            vec[128 + tid] = gam[l*DD + tid];
            vec[192 + tid] = bet[l*DD + tid];
        }
        /* stage W1 fp16 */
        for (int i = tid; i < DD*DD; i += 512)
            wbf[(i >> 6)*HS + (i & 63)] = __float2half_rn(W1l[i]);
        const float e1 = 1.f + eps[l];
        __syncthreads();

        /* gather -> h (fp32 math, fp16 store) */
        for (int i = tid; i < NN*DD; i += 512) {
            int n = i >> 6, d = i & 63;
            float a = e1 * xb[n*RS + d];
            if (n > 0) a += xb[ipar[n]*RS + d];
            int o1 = ioff[n+1];
            for (int j = ioff[n]; j < o1; j++) a += xb[ilist[j]*RS + d];
            hbf[n*HS + d] = __float2half_rn(a);
        }
        __syncthreads();

        /* matmul1: t = relu(h @ W1 + b1) -> hbf (in place) */
        for (int c0 = wrp; c0 < 25; c0 += 16) {
            int m0 = c0*16;
            float acc[8][4];
            #pragma unroll
            for (int nt = 0; nt < 8; nt++)
                #pragma unroll
                for (int q = 0; q < 4; q++) acc[nt][q] = 0.f;
            #pragma unroll
            for (int ks = 0; ks < 4; ks++) {
                u32 a0,a1,a2,a3;
                LDSM_X4(a0,a1,a2,a3, hbf_u + (((u32)m0 + a_row)*HS + (u32)ks*16 + a_kk)*2);
                u32 b[8][2];
                #pragma unroll
                for (int np = 0; np < 4; np++)
                    LDSM_X4_T(b[np*2][0], b[np*2][1], b[np*2+1][0], b[np*2+1][1],
                              wbf_u + (((u32)ks*16 + w_row)*HS + (u32)np*16 + w_col)*2);
                #pragma unroll
                for (int nt = 0; nt < 8; nt++)
                    MMA_F16(acc[nt][0],acc[nt][1],acc[nt][2],acc[nt][3],
                            a0,a1,a2,a3, b[nt][0],b[nt][1]);
            }
            int r0 = m0 + (lane >> 2), r1 = r0 + 8;
            #pragma unroll
            for (int nt = 0; nt < 8; nt++) {
                int col = nt*8 + (lane & 3)*2;
                float bb0 = vec[col], bb1 = vec[col+1];
                *(__half2*)&hbf[r0*HS + col] = __floats2half2_rn(
                    fmaxf(acc[nt][0] + bb0, 0.f), fmaxf(acc[nt][1] + bb1, 0.f));
                *(__half2*)&hbf[r1*HS + col] = __floats2half2_rn(
                    fmaxf(acc[nt][2] + bb0, 0.f), fmaxf(acc[nt][3] + bb1, 0.f));
            }
        }
        __syncthreads();

        /* stage W2 fp16 */
        for (int i = tid; i < DD*DD; i += 512)
            wbf[(i >> 6)*HS + (i & 63)] = __float2half_rn(W2l[i]);
        __syncthreads();

        /* matmul2 + residual + LayerNorm -> xb */
        for (int c0 = wrp; c0 < 25; c0 += 16) {
            int m0 = c0*16;
            float acc[8][4];
            #pragma unroll
            for (int nt = 0; nt < 8; nt++)
                #pragma unroll
                for (int q = 0; q < 4; q++) acc[nt][q] = 0.f;
            #pragma unroll
            for (int ks = 0; ks < 4; ks++) {
                u32 a0,a1,a2,a3;
                LDSM_X4(a0,a1,a2,a3, hbf_u + (((u32)m0 + a_row)*HS + (u32)ks*16 + a_kk)*2);
                u32 b[8][2];
                #pragma unroll
                for (int np = 0; np < 4; np++)
                    LDSM_X4_T(b[np*2][0], b[np*2][1], b[np*2+1][0], b[np*2+1][1],
                              wbf_u + (((u32)ks*16 + w_row)*HS + (u32)np*16 + w_col)*2);
                #pragma unroll
                for (int nt = 0; nt < 8; nt++)
                    MMA_F16(acc[nt][0],acc[nt][1],acc[nt][2],acc[nt][3],
                            a0,a1,a2,a3, b[nt][0],b[nt][1]);
            }
            int r0 = m0 + (lane >> 2), r1 = r0 + 8;
            float y0[16], y1[16];
            #pragma unroll
            for (int nt = 0; nt < 8; nt++) {
                int col = nt*8 + (lane & 3)*2;
                float b20 = vec[64+col], b21 = vec[64+col+1];
                y0[2*nt]   = acc[nt][0] + b20 + xb[r0*RS + col];
                y0[2*nt+1] = acc[nt][1] + b21 + xb[r0*RS + col+1];
                y1[2*nt]   = acc[nt][2] + b20 + xb[r1*RS + col];
                y1[2*nt+1] = acc[nt][3] + b21 + xb[r1*RS + col+1];
            }
            float s0 = 0.f, s1 = 0.f;
            #pragma unroll
            for (int q = 0; q < 16; q++) { s0 += y0[q]; s1 += y1[q]; }
            s0 += __shfl_xor_sync(0xffffffffu, s0, 1);
            s0 += __shfl_xor_sync(0xffffffffu, s0, 2);
            s1 += __shfl_xor_sync(0xffffffffu, s1, 1);
            s1 += __shfl_xor_sync(0xffffffffu, s1, 2);
            float mu0 = s0*(1.f/DD), mu1 = s1*(1.f/DD);
            float v0 = 0.f, v1 = 0.f;
            #pragma unroll
            for (int q = 0; q < 16; q++) {
                float d0 = y0[q]-mu0, d1 = y1[q]-mu1;
                v0 = fmaf(d0,d0,v0); v1 = fmaf(d1,d1,v1);
            }
            v0 += __shfl_xor_sync(0xffffffffu, v0, 1);
            v0 += __shfl_xor_sync(0xffffffffu, v0, 2);
            v1 += __shfl_xor_sync(0xffffffffu, v1, 1);
            v1 += __shfl_xor_sync(0xffffffffu, v1, 2);
            float rs0 = rsqrtf(v0*(1.f/DD) + 1e-5f);
            float rs1 = rsqrtf(v1*(1.f/DD) + 1e-5f);
            #pragma unroll
            for (int nt = 0; nt < 8; nt++) {
                int col = nt*8 + (lane & 3)*2;
                xb[r0*RS + col]   = (y0[2*nt]  -mu0)*rs0*vec[128+col]   + vec[192+col];
                xb[r0*RS + col+1] = (y0[2*nt+1]-mu0)*rs0*vec[128+col+1] + vec[192+col+1];
                xb[r1*RS + col]   = (y1[2*nt]  -mu1)*rs1*vec[128+col]   + vec[192+col];
                xb[r1*RS + col+1] = (y1[2*nt+1]-mu1)*rs1*vec[128+col+1] + vec[192+col+1];
            }
        }
        __syncthreads();
    }

    /* species pooling -> bf16 pool + fp32 valid */
    for (int i = tid; i < NSP*DD; i += 512) {
        int s = i >> 6, d = i & 63;
        int o0 = soff[s], o1 = soff[s+1];
        float a = 0.f;
        for (int j = o0; j < o1; j++) a += xb[slist[j]*RS + d];
        float c = (float)(o1 - o0);
        g_pool_bf[(size_t)s*NGT*DD + (size_t)g*DD + d] = __float2bfloat16(a / fmaxf(c, 1.f));
        if (d == 0) g_valid[s*NGT + g] = (c > 0.f) ? 1.f : 0.f;
    }
}

/* ====== kernel 2: per-(edge,tree) 1/ccnt (1 edge x 256 g per CTA) ======= */
__global__ void __launch_bounds__(256)
cnt_kernel(const u8* __restrict__ clade, const u8* __restrict__ leaf)
{
    __shared__ float msk[NSP];
    const int tid = threadIdx.x;
    const int e   = blockIdx.x;
    const int gg  = blockIdx.y * 256 + tid;
    const int bw  = leaf[1] ? 1 : (leaf[4] ? 4 : 8);
    if (tid < NSP)
        msk[tid] = clade[((size_t)e*NSP + tid)*(size_t)bw] ? 1.f : 0.f;
    __syncthreads();
    float c = 0.f;
    for (int s0 = 0; s0 < NSP; s0 += 8) {
        float v[8];
        #pragma unroll
        for (int q = 0; q < 8; q++) v[q] = g_valid[(s0+q)*NGT + gg];
        #pragma unroll
        for (int q = 0; q < 8; q++) c = fmaf(msk[s0+q], v[q], c);
    }
    g_minv[(size_t)e*NGT + gg] = (c > 0.f) ? (1.f/c) : 0.f;
}

/* =============== kernel 2b: build bf16 mask A [EPAD x KPAD] ============= */
__global__ void maskprep_kernel(const u8* __restrict__ clade, const u8* __restrict__ leaf)
{
    const int e = blockIdx.x, s = threadIdx.x;
    const int bw = leaf[1] ? 1 : (leaf[4] ? 4 : 8);
    float v = 0.f;
    if (e < NED && s < NSP && clade[((size_t)e*NSP + s)*(size_t)bw]) v = 1.f;
    g_maskA[(size_t)e*KPAD + s] = __float2bfloat16(v);
}

/* =========== kernel 2c: tiled transpose pool -> poolT [gd][s] =========== */
__global__ void __launch_bounds__(256)
transpose_kernel()
{
    __shared__ u16 t[32][40];
    const int tid = threadIdx.x;
    const int gd0 = blockIdx.x * 32;
    const int s0  = blockIdx.y * 32;
    for (int i = tid; i < 1024; i += 256) {
        int sr = i >> 5, gdc = i & 31;
        int s = s0 + sr;
        t[sr][gdc] = (s < NSP) ? *(const u16*)&g_pool_bf[(size_t)s*GTS + gd0 + gdc] : (u16)0;
    }
    __syncthreads();
    for (int i = tid; i < 1024; i += 256) {
        int gdr = i >> 5, sc = i & 31;
        *(u16*)&g_poolT[(size_t)(gd0 + gdr)*KPAD + s0 + sc] = t[sc][gdr];
    }
}

/* ====== kernel 3: mma.sync bf16 GEMM  C[e,gd] = sum_s M[e,s] P[gd,s] ==== */
#define APAD 264
#define SMA_OFF 0
#define SMB_OFF (128*APAD*2)
#define SMIV_OFF (SMB_OFF + 64*APAD*2)
#define SMG_TOT (SMIV_OFF + 128*4)

__global__ void __launch_bounds__(256, 1)
gemm_mma_kernel()
{
    extern __shared__ char smg[];
    const u32 smem = smem_u32(smg);
    __nv_bfloat16* smA = (__nv_bfloat16*)(smg + SMA_OFF);
    __nv_bfloat16* smB = (__nv_bfloat16*)(smg + SMB_OFF);
    float*         smIv= (float*)(smg + SMIV_OFF);

    const int tid  = threadIdx.x;
    const int lane = tid & 31, wrp = tid >> 5;
    const int wm   = wrp >> 1, wn = wrp & 1;
    const int gq    = blockIdx.x;
    const int etile = blockIdx.y;

    for (int i = tid; i < 128*32; i += 256) {
        int m = i >> 5, kq = i & 31;
        *(uint4*)&smA[m*APAD + kq*8] =
            *(const uint4*)&g_maskA[(size_t)(etile*128 + m)*KPAD + kq*8];
    }

    const u32 a_row = (u32)(wm*32 + (lane & 7) + ((lane >> 3) & 1)*8);
    const u32 a_kk  = (u32)((lane >> 4)*8);
    const u32 b_row = (u32)(wn*32 + (lane & 7) + (lane >> 4)*8);
    const u32 b_kk  = (u32)(((lane >> 3) & 1)*8);
    const u32 aBase = smem + SMA_OFF;
    const u32 bBase = smem + SMB_OFF;

    for (int gi = 0; gi < 4; gi++) {
        const int g = gq*4 + gi;
        __syncthreads();
        for (int i = tid; i < 64*32; i += 256) {
            int n = i >> 5, kq = i & 31;
            *(uint4*)&smB[n*APAD + kq*8] =
                *(const uint4*)&g_poolT[(size_t)(g*64 + n)*KPAD + kq*8];
        }
        if (tid < 128)
            smIv[tid] = g_minv[(size_t)(etile*128 + tid)*NGT + g];
        __syncthreads();

        float c[2][4][4];
        #pragma unroll
        for (int mf = 0; mf < 2; mf++)
            #pragma unroll
            for (int nf = 0; nf < 4; nf++)
                #pragma unroll
                for (int q = 0; q < 4; q++) c[mf][nf][q] = 0.f;

        #pragma unroll 4
        for (int ks = 0; ks < 16; ks++) {
            u32 a[2][4], b[4][2];
            #pragma unroll
            for (int mf = 0; mf < 2; mf++) {
                u32 ad = aBase + ((a_row + mf*16)*APAD + ks*16 + a_kk)*2;
                LDSM_X4(a[mf][0], a[mf][1], a[mf][2], a[mf][3], ad);
            }
            #pragma unroll
            for (int nh = 0; nh < 2; nh++) {
                u32 bd = bBase + ((b_row + nh*16)*APAD + ks*16 + b_kk)*2;
                LDSM_X4(b[nh*2][0], b[nh*2][1], b[nh*2+1][0], b[nh*2+1][1], bd);
            }
            #pragma unroll
            for (int mf = 0; mf < 2; mf++)
                #pragma unroll
                for (int nf = 0; nf < 4; nf++)
                    MMA_BF16(c[mf][nf][0], c[mf][nf][1], c[mf][nf][2], c[mf][nf][3],
                             a[mf][0], a[mf][1], a[mf][2], a[mf][3],
                             b[nf][0], b[nf][1]);
        }

        #pragma unroll
        for (int mf = 0; mf < 2; mf++) {
            int mLoc = wm*32 + mf*16 + (lane >> 2);
            int eLo = etile*128 + mLoc;
            int eHi = eLo + 8;
            float ivLo = smIv[mLoc], ivHi = smIv[mLoc + 8];
            #pragma unroll
            for (int nf = 0; nf < 4; nf++) {
                int d = wn*32 + nf*8 + (lane & 3)*2;
                if (eLo < NED) {
                    float2 v; v.x = c[mf][nf][0]*ivLo; v.y = c[mf][nf][1]*ivLo;
                    *(float2*)&g_gt[(size_t)eLo*GTS + g*64 + d] = v;
                }
                if (eHi < NED) {
                    float2 v; v.x = c[mf][nf][2]*ivHi; v.y = c[mf][nf][3]*ivHi;
                    *(float2*)&g_gt[(size_t)eHi*GTS + g*64 + d] = v;
                }
            }
        }
    }
}

/* ========= kernel 4: per-edge mean / unbiased std (single pass) ========= */
__global__ void __launch_bounds__(256, 4)
stats_kernel(float* __restrict__ out)
{
    __shared__ float red1[256], red2[256], redc[256];
    const int e = blockIdx.x, tid = threadIdx.x;
    const int d = tid & 63, part = tid >> 6;
    const float* gt = g_gt + (size_t)e*GTS;

    float s1 = 0.f, s2 = 0.f, cnt = 0.f;
    for (int gg = part*128; gg < part*128 + 128; gg++) {
        float x = gt[gg*DD + d];
        s1 += x;
        s2 = fmaf(x, x, s2);
        cnt += (g_minv[(size_t)e*NGT + gg] > 0.f) ? 1.f : 0.f;
    }
    red1[tid] = s1; red2[tid] = s2; redc[tid] = cnt;
    __syncthreads();
    if (tid < 64) {
        float nv = redc[d] + redc[64+d] + redc[128+d] + redc[192+d];
        float t1 = red1[d] + red1[64+d] + red1[128+d] + red1[192+d];
        float t2 = red2[d] + red2[64+d] + red2[128+d] + red2[192+d];
        float mn = t1 / fmaxf(nv, 1.f);
        float var = (t2 - nv*mn*mn) / fmaxf(nv - 1.f, 1.f);
        var = fmaxf(var, 0.f);
        out[(size_t)e*2*DD + d]      = mn;
        out[(size_t)e*2*DD + DD + d] = (nv > 1.f) ? sqrtf(var) : 0.f;
    }
}

/* ------------------------------ host -------------------------------------*/
extern "C" void kernel_launch(void* const* d_in, const int* in_sizes, int n_in,
                              void* d_out, int out_size)
{
    int o = (n_in > 5 && in_sizes[5] == (NSP+1)*DD) ? 0 : 1;

    const int* edge = (const int*)d_in[0];
    const int* sp   = (const int*)d_in[1];
    const u8*  leaf = (const u8*)d_in[2];
    const u8*  clad = (const u8*)d_in[4];
    const float* emb = (const float*)d_in[5+o];
    const float* W1  = (const float*)d_in[6+o];
    const float* b1  = (const float*)d_in[7+o];
    const float* W2  = (const float*)d_in[8+o];
    const float* b2  = (const float*)d_in[9+o];
    const float* eps = (const float*)d_in[10+o];
    const float* gam = (const float*)d_in[11+o];
    const float* bet = (const float*)d_in[12+o];

    cudaFuncSetAttribute(gin_kernel,      cudaFuncAttributeMaxDynamicSharedMemorySize, GIN_SMEM);
    cudaFuncSetAttribute(gemm_mma_kernel, cudaFuncAttributeMaxDynamicSharedMemorySize, SMG_TOT);

    gin_kernel<<<NGT, 512, GIN_SMEM>>>(edge, sp, leaf, emb, W1, b1, W2, b2, eps, gam, bet);
    maskprep_kernel<<<EPAD, KPAD>>>(clad, leaf);
    transpose_kernel<<<dim3(GTS/32, KPAD/32), 256>>>();
    cnt_kernel<<<dim3(NED, 2), 256>>>(clad, leaf);
    gemm_mma_kernel<<<dim3(128, 4), 256, SMG_TOT>>>();
    stats_kernel<<<NED, 256>>>((float*)d_out);
    (void)out_size; (void)n_in;
}